// round 2
// baseline (speedup 1.0000x reference)
#include <cuda_runtime.h>

// ---------------------------------------------------------------------------
// Problem constants (fixed by the dataset)
// ---------------------------------------------------------------------------
#define NMAX 50000
#define EMAX 800000

// ---------------------------------------------------------------------------
// Scratch (static __device__ arrays — no allocation allowed)
// ---------------------------------------------------------------------------
__device__ int   g_count[NMAX];
__device__ int   g_rowptr[NMAX + 1];
__device__ int   g_cursor[NMAX];
__device__ int   g_esrc[EMAX];
__device__ float g_mean[(size_t)NMAX * 128];  // layer1 uses [N,100], layer2 [N,128]
__device__ float g_t1[(size_t)NMAX * 128];    // pre-BN MLP1 activations
__device__ float g_t2[(size_t)NMAX * 64];     // pre-BN MLP2 activations
__device__ float g_s1[128], g_q1[128], g_s2[64], g_q2[64];     // BN sums / sumsq
__device__ float g_al1[128], g_bt1[128], g_al2[64], g_bt2[64]; // BN affine

// ---------------------------------------------------------------------------
// f32x2 packed-FMA helpers (FFMA2 — only reachable via PTX fma.rn.f32x2)
// ---------------------------------------------------------------------------
__device__ __forceinline__ void ffma2(unsigned long long& d,
                                      unsigned long long a,
                                      unsigned long long b) {
    asm("fma.rn.f32x2 %0, %1, %2, %0;" : "+l"(d) : "l"(a), "l"(b));
}
__device__ __forceinline__ unsigned long long dup2(float x) {
    unsigned int u = __float_as_uint(x);
    unsigned long long r;
    asm("mov.b64 %0, {%1, %1};" : "=l"(r) : "r"(u));
    return r;
}
__device__ __forceinline__ unsigned long long pk2(float x, float y) {
    unsigned int ux = __float_as_uint(x), uy = __float_as_uint(y);
    unsigned long long r;
    asm("mov.b64 %0, {%1, %2};" : "=l"(r) : "r"(ux), "r"(uy));
    return r;
}
__device__ __forceinline__ float2 unpk(unsigned long long v) {
    unsigned int lo, hi;
    asm("mov.b64 {%0, %1}, %2;" : "=r"(lo), "=r"(hi) : "l"(v));
    return make_float2(__uint_as_float(lo), __uint_as_float(hi));
}

// ---------------------------------------------------------------------------
// CSR build: zero -> histogram -> scan -> scatter
// ---------------------------------------------------------------------------
__global__ void k_zero(int n) {
    int i = blockIdx.x * blockDim.x + threadIdx.x;
    if (i < n) g_count[i] = 0;
    if (i < 128) { g_s1[i] = 0.f; g_q1[i] = 0.f; }
    if (i < 64)  { g_s2[i] = 0.f; g_q2[i] = 0.f; }
}

__global__ void k_hist(const int* __restrict__ dst, int E) {
    int i = blockIdx.x * blockDim.x + threadIdx.x;
    if (i < E) atomicAdd(&g_count[dst[i]], 1);
}

__global__ void k_scan(int N) {
    __shared__ int sums[1024];
    int t = threadIdx.x;
    int chunk = (N + 1023) >> 10;
    int b = t * chunk;
    int e = b + chunk; if (e > N) e = N;
    int s = 0;
    for (int i = b; i < e; i++) s += g_count[i];
    sums[t] = s;
    __syncthreads();
    int own = s;
    for (int off = 1; off < 1024; off <<= 1) {
        int v = (t >= off) ? sums[t - off] : 0;
        __syncthreads();
        sums[t] += v;
        __syncthreads();
    }
    int pre = sums[t] - own;  // exclusive prefix
    for (int i = b; i < e; i++) {
        g_rowptr[i] = pre;
        g_cursor[i] = pre;
        pre += g_count[i];
    }
    if (t == 1023) g_rowptr[N] = sums[1023];
}

__global__ void k_scatter(const int* __restrict__ src, const int* __restrict__ dst, int E) {
    int i = blockIdx.x * blockDim.x + threadIdx.x;
    if (i < E) {
        int d = dst[i];
        int p = atomicAdd(&g_cursor[d], 1);
        g_esrc[p] = src[i];
    }
}

// ---------------------------------------------------------------------------
// Mean aggregation: warp per node, gather via CSR, register accumulators.
// ---------------------------------------------------------------------------
template <int F>
__global__ void k_aggregate(const float* __restrict__ feat, float* __restrict__ mout, int N) {
    int g = blockIdx.x * blockDim.x + threadIdx.x;
    int w = g >> 5;
    int lane = g & 31;
    if (w >= N) return;
    int s = g_rowptr[w], e = g_rowptr[w + 1];
    constexpr int Q = F / 4;
    bool act = (lane < Q);
    int col = lane * 4;
    float ax = 0.f, ay = 0.f, az = 0.f, aw = 0.f;
    int src = (s < e) ? g_esrc[s] : 0;
    for (int i = s; i < e; i++) {
        int nsrc = (i + 1 < e) ? g_esrc[i + 1] : 0;  // 1-deep prefetch
        if (act) {
            float4 v = *(const float4*)&feat[(size_t)src * F + col];
            ax += v.x; ay += v.y; az += v.z; aw += v.w;
        }
        src = nsrc;
    }
    if (act) {
        float inv = (e > s) ? 1.f / (float)(e - s) : 0.f;  // deg=0 -> mean=0 (matches max(deg,1))
        float4 m = make_float4(ax * inv, ay * inv, az * inv, aw * inv);
        *(float4*)&mout[(size_t)w * F + col] = m;
    }
}

// ---------------------------------------------------------------------------
// Fused GEMM:  out[N, COLS] = relu_or_raw( [A1 | A2] @ [Wa ; Wb] + bias )
//   AMODE 0: A1 raw (and A2 raw if KB>0)
//   AMODE 2: A1 staged as relu(A1*alpha[k] + beta[k])   (BN-apply fusion)
//   STATS=false: relu + store (SAGE layers)
//   STATS=true : raw store + per-column sum/sumsq accumulation (pre-BN MLP)
// Block: 256 threads, thread tile 4 rows x 4 cols, weights + A tile in SMEM,
// inner loop uses packed fma.rn.f32x2 (2 FMA / instr).
// ---------------------------------------------------------------------------
template <int KA, int KB, int COLS, int AMODE, bool STATS>
__global__ void k_gemm(const float* __restrict__ A1, const float* __restrict__ A2,
                       const float* __restrict__ alpha, const float* __restrict__ beta,
                       const float* __restrict__ Wa, const float* __restrict__ Wb,
                       const float* __restrict__ bias,
                       float* __restrict__ outp,
                       float* __restrict__ statS, float* __restrict__ statQ,
                       int N) {
    constexpr int K = KA + KB;
    constexpr int CG = COLS / 4;   // column groups
    constexpr int RG = 256 / CG;   // row groups
    constexpr int ROWS = RG * 4;   // rows per tile
    constexpr int AS = ROWS + 4;   // padded A stride (keeps 16B alignment, breaks conflicts)

    extern __shared__ float sm[];
    float* W_s = sm;                 // [K][COLS]
    float* A_s = sm + K * COLS;      // [K][AS]

    int tid = threadIdx.x;

    // Load weights once per block (float4)
    for (int i = tid; i < K * CG; i += 256) {
        int k = i / CG, c4 = i % CG;
        float4 v;
        if (KB > 0 && k >= KA) v = ((const float4*)Wb)[(k - KA) * CG + c4];
        else                   v = ((const float4*)Wa)[k * CG + c4];
        ((float4*)W_s)[i] = v;
    }

    int cx = tid % CG, ry = tid / CG;
    int c0 = cx * 4, r0 = ry * 4;

    unsigned long long bias01 = pk2(bias[c0], bias[c0 + 1]);
    unsigned long long bias23 = pk2(bias[c0 + 2], bias[c0 + 3]);

    float ts[4] = {0.f, 0.f, 0.f, 0.f}, tq[4] = {0.f, 0.f, 0.f, 0.f};

    for (int t0 = blockIdx.x * ROWS; t0 < N; t0 += gridDim.x * ROWS) {
        __syncthreads();  // protect A_s from previous tile's readers
        // Stage A (transposed [k][row]) — coalesced global reads
        for (int i = tid; i < ROWS * KA; i += 256) {
            int r = i / KA, k = i % KA;
            int row = t0 + r;
            float v = 0.f;
            if (row < N) {
                v = A1[(size_t)row * KA + k];
                if (AMODE == 2) v = fmaxf(v * alpha[k] + beta[k], 0.f);
            }
            A_s[k * AS + r] = v;
        }
        if (KB > 0) {
            for (int i = tid; i < ROWS * KB; i += 256) {
                int r = i / KB, k = i % KB;
                int row = t0 + r;
                A_s[(KA + k) * AS + r] = (row < N) ? A2[(size_t)row * KB + k] : 0.f;
            }
        }
        __syncthreads();

        unsigned long long acc01[4], acc23[4];
#pragma unroll
        for (int i = 0; i < 4; i++) { acc01[i] = bias01; acc23[i] = bias23; }

#pragma unroll 8
        for (int k = 0; k < K; k++) {
            float4 a = *(const float4*)&A_s[k * AS + r0];          // broadcast within warp
            ulonglong2 w = *(const ulonglong2*)&W_s[k * COLS + c0]; // 2 packed col-pairs
            unsigned long long d0 = dup2(a.x), d1 = dup2(a.y), d2 = dup2(a.z), d3 = dup2(a.w);
            ffma2(acc01[0], d0, w.x); ffma2(acc23[0], d0, w.y);
            ffma2(acc01[1], d1, w.x); ffma2(acc23[1], d1, w.y);
            ffma2(acc01[2], d2, w.x); ffma2(acc23[2], d2, w.y);
            ffma2(acc01[3], d3, w.x); ffma2(acc23[3], d3, w.y);
        }

#pragma unroll
        for (int i = 0; i < 4; i++) {
            int row = t0 + r0 + i;
            if (row < N) {
                float2 p01 = unpk(acc01[i]), p23 = unpk(acc23[i]);
                float4 o;
                if (!STATS) {
                    o = make_float4(fmaxf(p01.x, 0.f), fmaxf(p01.y, 0.f),
                                    fmaxf(p23.x, 0.f), fmaxf(p23.y, 0.f));
                } else {
                    o = make_float4(p01.x, p01.y, p23.x, p23.y);
                    ts[0] += o.x; tq[0] += o.x * o.x;
                    ts[1] += o.y; tq[1] += o.y * o.y;
                    ts[2] += o.z; tq[2] += o.z * o.z;
                    ts[3] += o.w; tq[3] += o.w * o.w;
                }
                *(float4*)&outp[(size_t)row * COLS + c0] = o;
            }
        }
    }

    if (STATS) {
#pragma unroll
        for (int j = 0; j < 4; j++) {
            atomicAdd(&statS[c0 + j], ts[j]);
            atomicAdd(&statQ[c0 + j], tq[j]);
        }
    }
}

// ---------------------------------------------------------------------------
// BN finalize: alpha = gamma * rsqrt(var + eps), beta' = beta - mean*alpha
// ---------------------------------------------------------------------------
__global__ void k_bnfin(const float* __restrict__ s, const float* __restrict__ q,
                        const float* __restrict__ gam, const float* __restrict__ bet,
                        float* __restrict__ al, float* __restrict__ bt,
                        int C, float invN) {
    int c = threadIdx.x;
    if (c < C) {
        float m = s[c] * invN;
        float v = q[c] * invN - m * m;
        float a = gam[c] * rsqrtf(v + 1e-5f);
        al[c] = a;
        bt[c] = bet[c] - m * a;
    }
}

// ---------------------------------------------------------------------------
// Final head: out[i] = relu(BN2(t2[i])) . W3 + b3   (warp per node)
// ---------------------------------------------------------------------------
__global__ void k_final(const float* __restrict__ W3, const float* __restrict__ b3,
                        float* __restrict__ out, int N) {
    int g = blockIdx.x * blockDim.x + threadIdx.x;
    int w = g >> 5;
    int lane = g & 31;
    if (w >= N) return;
    float ta = g_t2[(size_t)w * 64 + lane];
    float tb = g_t2[(size_t)w * 64 + 32 + lane];
    float za = fmaxf(ta * g_al2[lane] + g_bt2[lane], 0.f);
    float zb = fmaxf(tb * g_al2[lane + 32] + g_bt2[lane + 32], 0.f);
    float p = za * W3[lane] + zb * W3[lane + 32];
#pragma unroll
    for (int o = 16; o > 0; o >>= 1) p += __shfl_xor_sync(0xffffffffu, p, o);
    if (lane == 0) out[w] = p + b3[0];
}

// ---------------------------------------------------------------------------
// Host launcher
// ---------------------------------------------------------------------------
extern "C" void kernel_launch(void* const* d_in, const int* in_sizes, int n_in,
                              void* d_out, int out_size) {
    const float* x   = (const float*)d_in[0];
    const int*   ei  = (const int*)d_in[1];
    const float* Wl1 = (const float*)d_in[2];
    const float* bl1 = (const float*)d_in[3];
    const float* Wr1 = (const float*)d_in[4];
    const float* Wl2 = (const float*)d_in[5];
    const float* bl2 = (const float*)d_in[6];
    const float* Wr2 = (const float*)d_in[7];
    const float* W1  = (const float*)d_in[8];
    const float* b1  = (const float*)d_in[9];
    const float* g1  = (const float*)d_in[10];
    const float* be1 = (const float*)d_in[11];
    const float* W2  = (const float*)d_in[12];
    const float* b2  = (const float*)d_in[13];
    const float* g2  = (const float*)d_in[14];
    const float* be2 = (const float*)d_in[15];
    const float* W3  = (const float*)d_in[16];
    const float* b3  = (const float*)d_in[17];

    int N = in_sizes[0] / 100;
    int E = in_sizes[1] / 2;
    const int* src = ei;
    const int* dst = ei + E;

    float* out = (float*)d_out;
    float* h1  = out + N;
    float* h2  = h1 + (size_t)N * 128;

    // Scratch symbol addresses
    float *p_mean, *p_t1, *p_t2, *p_s1, *p_q1, *p_s2, *p_q2, *p_al1, *p_bt1, *p_al2, *p_bt2;
    cudaGetSymbolAddress((void**)&p_mean, g_mean);
    cudaGetSymbolAddress((void**)&p_t1, g_t1);
    cudaGetSymbolAddress((void**)&p_t2, g_t2);
    cudaGetSymbolAddress((void**)&p_s1, g_s1);
    cudaGetSymbolAddress((void**)&p_q1, g_q1);
    cudaGetSymbolAddress((void**)&p_s2, g_s2);
    cudaGetSymbolAddress((void**)&p_q2, g_q2);
    cudaGetSymbolAddress((void**)&p_al1, g_al1);
    cudaGetSymbolAddress((void**)&p_bt1, g_bt1);
    cudaGetSymbolAddress((void**)&p_al2, g_al2);
    cudaGetSymbolAddress((void**)&p_bt2, g_bt2);

    // Dynamic SMEM sizes: (K*COLS + K*(ROWS+4)) * 4 bytes
    const int SM_S1 = (200 * 128 + 200 * 36) * 4;  // 131200
    const int SM_S2 = (256 * 128 + 256 * 36) * 4;  // 167936
    const int SM_M1 = (128 * 128 + 128 * 36) * 4;  //  83968
    const int SM_M2 = (128 * 64 + 128 * 68) * 4;   //  67584

    cudaFuncSetAttribute(k_gemm<100, 100, 128, 0, false>,
                         cudaFuncAttributeMaxDynamicSharedMemorySize, SM_S1);
    cudaFuncSetAttribute(k_gemm<128, 128, 128, 0, false>,
                         cudaFuncAttributeMaxDynamicSharedMemorySize, SM_S2);
    cudaFuncSetAttribute(k_gemm<128, 0, 128, 0, true>,
                         cudaFuncAttributeMaxDynamicSharedMemorySize, SM_M1);
    cudaFuncSetAttribute(k_gemm<128, 0, 64, 2, true>,
                         cudaFuncAttributeMaxDynamicSharedMemorySize, SM_M2);

    // --- CSR build (once; reused by both SAGE layers) ---
    k_zero<<<(N + 255) / 256, 256>>>(N);
    k_hist<<<(E + 255) / 256, 256>>>(dst, E);
    k_scan<<<1, 1024>>>(N);
    k_scatter<<<(E + 255) / 256, 256>>>(src, dst, E);

    // --- SAGE layer 1 ---
    k_aggregate<100><<<(N + 7) / 8, 256>>>(x, p_mean, N);
    k_gemm<100, 100, 128, 0, false><<<148, 256, SM_S1>>>(
        p_mean, x, nullptr, nullptr, Wl1, Wr1, bl1, h1, nullptr, nullptr, N);

    // --- SAGE layer 2 ---
    k_aggregate<128><<<(N + 7) / 8, 256>>>(h1, p_mean, N);
    k_gemm<128, 128, 128, 0, false><<<148, 256, SM_S2>>>(
        p_mean, h1, nullptr, nullptr, Wl2, Wr2, bl2, h2, nullptr, nullptr, N);

    // --- MLP layer 1 (pre-BN t1 + column stats) ---
    k_gemm<128, 0, 128, 0, true><<<296, 256, SM_M1>>>(
        h2, nullptr, nullptr, nullptr, W1, nullptr, b1, p_t1, p_s1, p_q1, N);
    k_bnfin<<<1, 128>>>(p_s1, p_q1, g1, be1, p_al1, p_bt1, 128, 1.f / (float)N);

    // --- MLP layer 2 (BN1+relu fused into A staging; pre-BN t2 + stats) ---
    k_gemm<128, 0, 64, 2, true><<<444, 256, SM_M2>>>(
        p_t1, nullptr, p_al1, p_bt1, W2, nullptr, b2, p_t2, p_s2, p_q2, N);
    k_bnfin<<<1, 64>>>(p_s2, p_q2, g2, be2, p_al2, p_bt2, 64, 1.f / (float)N);

    // --- Head: BN2+relu+dot fused ---
    k_final<<<(N + 7) / 8, 256>>>(W3, b3, out, N);
}

// round 5
// speedup vs baseline: 1.1582x; 1.1582x over previous
#include <cuda_runtime.h>
#include <cstdint>

// ---------------------------------------------------------------------------
// Problem constants (fixed by the dataset)
// ---------------------------------------------------------------------------
#define NMAX 50000
#define EMAX 800000

// ---------------------------------------------------------------------------
// Scratch (static __device__ arrays — no allocation allowed)
// ---------------------------------------------------------------------------
__device__ int   g_count[NMAX];
__device__ int   g_rowptr[NMAX + 1];
__device__ int   g_cursor[NMAX];
__device__ int   g_esrc[EMAX];
__device__ float g_mean[(size_t)NMAX * 128];  // layer1 uses [N,100], layer2 [N,128]
__device__ float g_t1[(size_t)NMAX * 128];    // sage accum scratch, then pre-BN MLP1
__device__ float g_t2[(size_t)NMAX * 64];     // pre-BN MLP2 activations
__device__ float g_s1[128], g_q1[128], g_s2[64], g_q2[64];     // BN sums / sumsq
__device__ float g_al1[128], g_bt1[128], g_al2[64], g_bt2[64]; // BN affine

// ---------------------------------------------------------------------------
// tf32 helpers
// ---------------------------------------------------------------------------
__device__ __forceinline__ uint32_t f2tf(float x) {
    uint32_t r;
    asm("cvt.rna.tf32.f32 %0, %1;" : "=r"(r) : "f"(x));
    return r;
}
// hi/lo split for 3xTF32: v = hi + lo (both tf32-representable)
__device__ __forceinline__ uint2 split_tf32(float v) {
    uint32_t hi = f2tf(v);
    float vlo = v - __uint_as_float(hi);
    uint32_t lo = f2tf(vlo);
    return make_uint2(hi, lo);
}
__device__ __forceinline__ void mma_tf32(float* c,
                                         uint32_t a0, uint32_t a1, uint32_t a2, uint32_t a3,
                                         uint32_t b0, uint32_t b1) {
    asm volatile(
        "mma.sync.aligned.m16n8k8.row.col.f32.tf32.tf32.f32 "
        "{%0,%1,%2,%3}, {%4,%5,%6,%7}, {%8,%9}, {%0,%1,%2,%3};"
        : "+f"(c[0]), "+f"(c[1]), "+f"(c[2]), "+f"(c[3])
        : "r"(a0), "r"(a1), "r"(a2), "r"(a3), "r"(b0), "r"(b1));
}

// ---------------------------------------------------------------------------
// CSR build: zero -> histogram -> scan -> scatter
// ---------------------------------------------------------------------------
__global__ void k_zero(int n) {
    int i = blockIdx.x * blockDim.x + threadIdx.x;
    if (i < n) g_count[i] = 0;
    if (i < 128) { g_s1[i] = 0.f; g_q1[i] = 0.f; }
    if (i < 64)  { g_s2[i] = 0.f; g_q2[i] = 0.f; }
}

__global__ void k_hist(const int* __restrict__ dst, int E) {
    int i = blockIdx.x * blockDim.x + threadIdx.x;
    if (i < E) atomicAdd(&g_count[dst[i]], 1);
}

__global__ void k_scan(int N) {
    __shared__ int sums[1024];
    int t = threadIdx.x;
    int chunk = (N + 1023) >> 10;
    int b = t * chunk;
    int e = b + chunk; if (e > N) e = N;
    int s = 0;
    for (int i = b; i < e; i++) s += g_count[i];
    sums[t] = s;
    __syncthreads();
    int own = s;
    for (int off = 1; off < 1024; off <<= 1) {
        int v = (t >= off) ? sums[t - off] : 0;
        __syncthreads();
        sums[t] += v;
        __syncthreads();
    }
    int pre = sums[t] - own;  // exclusive prefix
    for (int i = b; i < e; i++) {
        g_rowptr[i] = pre;
        g_cursor[i] = pre;
        pre += g_count[i];
    }
    if (t == 1023) g_rowptr[N] = sums[1023];
}

__global__ void k_scatter(const int* __restrict__ src, const int* __restrict__ dst, int E) {
    int i = blockIdx.x * blockDim.x + threadIdx.x;
    if (i < E) {
        int d = dst[i];
        int p = atomicAdd(&g_cursor[d], 1);
        g_esrc[p] = src[i];
    }
}

// ---------------------------------------------------------------------------
// Mean aggregation: warp per node, gather via CSR, register accumulators.
// ---------------------------------------------------------------------------
template <int F>
__global__ void k_aggregate(const float* __restrict__ feat, float* __restrict__ mout, int N) {
    int g = blockIdx.x * blockDim.x + threadIdx.x;
    int w = g >> 5;
    int lane = g & 31;
    if (w >= N) return;
    int s = g_rowptr[w], e = g_rowptr[w + 1];
    constexpr int Q = F / 4;
    bool act = (lane < Q);
    int col = lane * 4;
    float ax = 0.f, ay = 0.f, az = 0.f, aw = 0.f;
    int src = (s < e) ? g_esrc[s] : 0;
    for (int i = s; i < e; i++) {
        int nsrc = (i + 1 < e) ? g_esrc[i + 1] : 0;  // 1-deep prefetch
        if (act) {
            float4 v = *(const float4*)&feat[(size_t)src * F + col];
            ax += v.x; ay += v.y; az += v.z; aw += v.w;
        }
        src = nsrc;
    }
    if (act) {
        float inv = (e > s) ? 1.f / (float)(e - s) : 0.f;  // deg=0 -> mean=0 (matches max(deg,1))
        float4 m = make_float4(ax * inv, ay * inv, az * inv, aw * inv);
        *(float4*)&mout[(size_t)w * F + col] = m;
    }
}

// ---------------------------------------------------------------------------
// Fused tensor-core GEMM, 3xTF32 (hi/lo split -> near-fp32 precision):
//   EPI 0 (RAW):     outp = A @ W                      (sage pass 1 -> scratch)
//   EPI 1 (ADDRELU): outp = relu(A @ W + accum + bias) (sage pass 2)
//   EPI 2 (STATS):   outp = A @ W + bias, + column sum/sumsq accumulation
//   AMODE 2: A staged as relu(A*alpha[k]+beta[k]) (BN-apply fusion, mlp2)
// Block 256 threads (8 warps = 2 row-groups x 4 col-groups), tile 64 x COLS.
// W resident in SMEM as tf32 (hi,lo) interleaved [COLS][SA][2]; A staged per
// tile as [64][SA][2]. SA % 16 == 4 -> all LDS.64 fragment loads conflict-free.
// Per k-step: 3 MMAs (lo*hi, hi*lo, hi*hi).
// ---------------------------------------------------------------------------
template <int K, int COLS, int AMODE, int EPI>
__global__ void __launch_bounds__(256)
k_gemm(const float* __restrict__ A,
       const float* __restrict__ alpha, const float* __restrict__ beta,
       const float* __restrict__ W, const float* __restrict__ bias,
       const float* __restrict__ accum,
       float* __restrict__ outp,
       float* __restrict__ statS, float* __restrict__ statQ,
       int N) {
    constexpr int KP = ((K + 7) / 8) * 8;           // padded K (multiple of 8)
    constexpr int SA = ((K + 15) / 16) * 16 + 4;    // stride: %16 == 4 -> conflict-free
    constexpr int BM = 64;
    constexpr int WCOLS = COLS / 4;   // warp column span (32 or 16)
    constexpr int NT = WCOLS / 8;     // n-tiles per warp
    constexpr int MT = 2;             // m-tiles per warp (32 rows)

    extern __shared__ uint32_t sm_u[];
    uint32_t* Wt = sm_u;                   // [COLS][SA][2] (hi,lo)
    uint32_t* As = sm_u + COLS * SA * 2;   // [BM][SA][2]

    int tid = threadIdx.x;
    int lane = tid & 31, wid = tid >> 5;
    int wr = wid & 1, wc = wid >> 1;        // row-group {0,1}, col-group {0..3}
    int gid = lane >> 2, tig = lane & 3;    // mma fragment coords

    // Stage W once (transposed, hi/lo tf32)
    for (int i = tid; i < KP * COLS; i += 256) {
        int k = i / COLS, c = i % COLS;
        float v = (k < K) ? W[k * COLS + c] : 0.f;
        *(uint2*)&Wt[(c * SA + k) * 2] = split_tf32(v);
    }

    // Bias cache (per-thread column pairs); EPI 0 has no bias
    float bs0[NT], bs1[NT];
#pragma unroll
    for (int nt = 0; nt < NT; nt++) {
        int c = wc * WCOLS + nt * 8 + 2 * tig;
        bs0[nt] = (EPI != 0) ? bias[c] : 0.f;
        bs1[nt] = (EPI != 0) ? bias[c + 1] : 0.f;
    }

    float sS[NT * 2], sQ[NT * 2];
#pragma unroll
    for (int j = 0; j < NT * 2; j++) { sS[j] = 0.f; sQ[j] = 0.f; }

    for (int t0 = blockIdx.x * BM; t0 < N; t0 += gridDim.x * BM) {
        __syncthreads();  // protect As from previous tile's readers
        // Stage A tile (hi/lo interleaved). STS.64, coalesced along k.
        for (int i = tid; i < BM * KP; i += 256) {
            int r = i / KP, k = i % KP;
            int row = t0 + r;
            float v = 0.f;
            if (row < N && k < K) {
                v = A[(size_t)row * K + k];
                if (AMODE == 2) v = fmaxf(fmaf(v, alpha[k], beta[k]), 0.f);
            }
            *(uint2*)&As[(r * SA + k) * 2] = split_tf32(v);
        }
        __syncthreads();

        float acc[MT][NT][4];
#pragma unroll
        for (int mt = 0; mt < MT; mt++)
#pragma unroll
            for (int nt = 0; nt < NT; nt++)
#pragma unroll
                for (int j = 0; j < 4; j++) acc[mt][nt][j] = 0.f;

#pragma unroll 2
        for (int k0 = 0; k0 < KP; k0 += 8) {
            uint2 a0[MT], a1[MT], a2[MT], a3[MT];   // .x = hi, .y = lo
#pragma unroll
            for (int mt = 0; mt < MT; mt++) {
                const uint32_t* p = As + ((wr * 32 + mt * 16 + gid) * SA + k0 + tig) * 2;
                a0[mt] = *(const uint2*)(p);
                a1[mt] = *(const uint2*)(p + 16 * SA);   // row + 8
                a2[mt] = *(const uint2*)(p + 8);         // k + 4
                a3[mt] = *(const uint2*)(p + 16 * SA + 8);
            }
#pragma unroll
            for (int nt = 0; nt < NT; nt++) {
                const uint32_t* q = Wt + ((wc * WCOLS + nt * 8 + gid) * SA + k0 + tig) * 2;
                uint2 b0 = *(const uint2*)(q);
                uint2 b1 = *(const uint2*)(q + 8);       // k + 4
#pragma unroll
                for (int mt = 0; mt < MT; mt++) {
                    // 3xTF32: corrections first, main term last
                    mma_tf32(acc[mt][nt], a0[mt].y, a1[mt].y, a2[mt].y, a3[mt].y, b0.x, b1.x);
                    mma_tf32(acc[mt][nt], a0[mt].x, a1[mt].x, a2[mt].x, a3[mt].x, b0.y, b1.y);
                    mma_tf32(acc[mt][nt], a0[mt].x, a1[mt].x, a2[mt].x, a3[mt].x, b0.x, b1.x);
                }
            }
        }

        // Epilogue
#pragma unroll
        for (int mt = 0; mt < MT; mt++) {
            int r0 = t0 + wr * 32 + mt * 16 + gid;  // c0/c1 row
            int r1 = r0 + 8;                        // c2/c3 row
#pragma unroll
            for (int nt = 0; nt < NT; nt++) {
                int col = wc * WCOLS + nt * 8 + 2 * tig;
                float o0 = acc[mt][nt][0] + bs0[nt];
                float o1 = acc[mt][nt][1] + bs1[nt];
                float o2 = acc[mt][nt][2] + bs0[nt];
                float o3 = acc[mt][nt][3] + bs1[nt];
                if (r0 < N) {
                    if (EPI == 1) {
                        float2 ac = *(const float2*)&accum[(size_t)r0 * COLS + col];
                        o0 = fmaxf(o0 + ac.x, 0.f);
                        o1 = fmaxf(o1 + ac.y, 0.f);
                    }
                    if (EPI == 2) {
                        sS[nt * 2]     += o0; sQ[nt * 2]     += o0 * o0;
                        sS[nt * 2 + 1] += o1; sQ[nt * 2 + 1] += o1 * o1;
                    }
                    *(float2*)&outp[(size_t)r0 * COLS + col] = make_float2(o0, o1);
                }
                if (r1 < N) {
                    if (EPI == 1) {
                        float2 ac = *(const float2*)&accum[(size_t)r1 * COLS + col];
                        o2 = fmaxf(o2 + ac.x, 0.f);
                        o3 = fmaxf(o3 + ac.y, 0.f);
                    }
                    if (EPI == 2) {
                        sS[nt * 2]     += o2; sQ[nt * 2]     += o2 * o2;
                        sS[nt * 2 + 1] += o3; sQ[nt * 2 + 1] += o3 * o3;
                    }
                    *(float2*)&outp[(size_t)r1 * COLS + col] = make_float2(o2, o3);
                }
            }
        }
    }

    if (EPI == 2) {
        // Lanes sharing a column are {tig, tig+4, ..., tig+28}: xor-reduce over 4,8,16
#pragma unroll
        for (int j = 0; j < NT * 2; j++) {
            float s = sS[j], q = sQ[j];
#pragma unroll
            for (int o = 4; o < 32; o <<= 1) {
                s += __shfl_xor_sync(0xffffffffu, s, o);
                q += __shfl_xor_sync(0xffffffffu, q, o);
            }
            if (gid == 0) {
                int col = wc * WCOLS + (j >> 1) * 8 + 2 * tig + (j & 1);
                atomicAdd(&statS[col], s);
                atomicAdd(&statQ[col], q);
            }
        }
    }
}

// ---------------------------------------------------------------------------
// BN finalize: alpha = gamma * rsqrt(var + eps), beta' = beta - mean*alpha
// ---------------------------------------------------------------------------
__global__ void k_bnfin(const float* __restrict__ s, const float* __restrict__ q,
                        const float* __restrict__ gam, const float* __restrict__ bet,
                        float* __restrict__ al, float* __restrict__ bt,
                        int C, float invN) {
    int c = threadIdx.x;
    if (c < C) {
        float m = s[c] * invN;
        float v = q[c] * invN - m * m;
        float a = gam[c] * rsqrtf(v + 1e-5f);
        al[c] = a;
        bt[c] = bet[c] - m * a;
    }
}

// ---------------------------------------------------------------------------
// Final head: out[i] = relu(BN2(t2[i])) . W3 + b3   (warp per node)
// ---------------------------------------------------------------------------
__global__ void k_final(const float* __restrict__ W3, const float* __restrict__ b3,
                        float* __restrict__ out, int N) {
    int g = blockIdx.x * blockDim.x + threadIdx.x;
    int w = g >> 5;
    int lane = g & 31;
    if (w >= N) return;
    float ta = g_t2[(size_t)w * 64 + lane];
    float tb = g_t2[(size_t)w * 64 + 32 + lane];
    float za = fmaxf(ta * g_al2[lane] + g_bt2[lane], 0.f);
    float zb = fmaxf(tb * g_al2[lane + 32] + g_bt2[lane + 32], 0.f);
    float p = za * W3[lane] + zb * W3[lane + 32];
#pragma unroll
    for (int o = 16; o > 0; o >>= 1) p += __shfl_xor_sync(0xffffffffu, p, o);
    if (lane == 0) out[w] = p + b3[0];
}

// ---------------------------------------------------------------------------
// Host launcher
// ---------------------------------------------------------------------------
extern "C" void kernel_launch(void* const* d_in, const int* in_sizes, int n_in,
                              void* d_out, int out_size) {
    const float* x   = (const float*)d_in[0];
    const int*   ei  = (const int*)d_in[1];
    const float* Wl1 = (const float*)d_in[2];
    const float* bl1 = (const float*)d_in[3];
    const float* Wr1 = (const float*)d_in[4];
    const float* Wl2 = (const float*)d_in[5];
    const float* bl2 = (const float*)d_in[6];
    const float* Wr2 = (const float*)d_in[7];
    const float* W1  = (const float*)d_in[8];
    const float* b1  = (const float*)d_in[9];
    const float* g1  = (const float*)d_in[10];
    const float* be1 = (const float*)d_in[11];
    const float* W2  = (const float*)d_in[12];
    const float* b2  = (const float*)d_in[13];
    const float* g2  = (const float*)d_in[14];
    const float* be2 = (const float*)d_in[15];
    const float* W3  = (const float*)d_in[16];
    const float* b3  = (const float*)d_in[17];

    int N = in_sizes[0] / 100;
    int E = in_sizes[1] / 2;
    const int* src = ei;
    const int* dst = ei + E;

    float* out = (float*)d_out;
    float* h1  = out + N;
    float* h2  = h1 + (size_t)N * 128;

    // Scratch symbol addresses
    float *p_mean, *p_t1, *p_t2, *p_s1, *p_q1, *p_s2, *p_q2, *p_al1, *p_bt1, *p_al2, *p_bt2;
    cudaGetSymbolAddress((void**)&p_mean, g_mean);
    cudaGetSymbolAddress((void**)&p_t1, g_t1);
    cudaGetSymbolAddress((void**)&p_t2, g_t2);
    cudaGetSymbolAddress((void**)&p_s1, g_s1);
    cudaGetSymbolAddress((void**)&p_q1, g_q1);
    cudaGetSymbolAddress((void**)&p_s2, g_s2);
    cudaGetSymbolAddress((void**)&p_q2, g_q2);
    cudaGetSymbolAddress((void**)&p_al1, g_al1);
    cudaGetSymbolAddress((void**)&p_bt1, g_bt1);
    cudaGetSymbolAddress((void**)&p_al2, g_al2);
    cudaGetSymbolAddress((void**)&p_bt2, g_bt2);

    // Dynamic SMEM: (COLS + 64) * SA * 2 * 4 bytes
    const int SM_K100 = (128 + 64) * 116 * 8;  // 178176  (K=100 -> SA=116)
    const int SM_K128 = (128 + 64) * 132 * 8;  // 202752  (K=128 -> SA=132)
    const int SM_M2   = (64 + 64) * 132 * 8;   // 135168

    cudaFuncSetAttribute(k_gemm<100, 128, 0, 0>,
                         cudaFuncAttributeMaxDynamicSharedMemorySize, SM_K100);
    cudaFuncSetAttribute(k_gemm<100, 128, 0, 1>,
                         cudaFuncAttributeMaxDynamicSharedMemorySize, SM_K100);
    cudaFuncSetAttribute(k_gemm<128, 128, 0, 0>,
                         cudaFuncAttributeMaxDynamicSharedMemorySize, SM_K128);
    cudaFuncSetAttribute(k_gemm<128, 128, 0, 1>,
                         cudaFuncAttributeMaxDynamicSharedMemorySize, SM_K128);
    cudaFuncSetAttribute(k_gemm<128, 128, 0, 2>,
                         cudaFuncAttributeMaxDynamicSharedMemorySize, SM_K128);
    cudaFuncSetAttribute(k_gemm<128, 64, 2, 2>,
                         cudaFuncAttributeMaxDynamicSharedMemorySize, SM_M2);

    // --- CSR build (once; reused by both SAGE layers) ---
    k_zero<<<(N + 255) / 256, 256>>>(N);
    k_hist<<<(E + 255) / 256, 256>>>(dst, E);
    k_scan<<<1, 1024>>>(N);
    k_scatter<<<(E + 255) / 256, 256>>>(src, dst, E);

    // --- SAGE layer 1: h1 = relu(mean@Wl1 + x@Wr1 + bl1) ---
    k_aggregate<100><<<(N + 7) / 8, 256>>>(x, p_mean, N);
    k_gemm<100, 128, 0, 0><<<148, 256, SM_K100>>>(
        p_mean, nullptr, nullptr, Wl1, nullptr, nullptr, p_t1, nullptr, nullptr, N);
    k_gemm<100, 128, 0, 1><<<148, 256, SM_K100>>>(
        x, nullptr, nullptr, Wr1, bl1, p_t1, h1, nullptr, nullptr, N);

    // --- SAGE layer 2: h2 = relu(mean(h1)@Wl2 + h1@Wr2 + bl2) ---
    k_aggregate<128><<<(N + 7) / 8, 256>>>(h1, p_mean, N);
    k_gemm<128, 128, 0, 0><<<148, 256, SM_K128>>>(
        p_mean, nullptr, nullptr, Wl2, nullptr, nullptr, p_t1, nullptr, nullptr, N);
    k_gemm<128, 128, 0, 1><<<148, 256, SM_K128>>>(
        h1, nullptr, nullptr, Wr2, bl2, p_t1, h2, nullptr, nullptr, N);

    // --- MLP layer 1 (pre-BN t1 + column stats) ---
    k_gemm<128, 128, 0, 2><<<148, 256, SM_K128>>>(
        h2, nullptr, nullptr, W1, b1, nullptr, p_t1, p_s1, p_q1, N);
    k_bnfin<<<1, 128>>>(p_s1, p_q1, g1, be1, p_al1, p_bt1, 128, 1.f / (float)N);

    // --- MLP layer 2 (BN1+relu fused into A staging; pre-BN t2 + stats) ---
    k_gemm<128, 64, 2, 2><<<148, 256, SM_M2>>>(
        p_t1, p_al1, p_bt1, W2, b2, nullptr, p_t2, p_s2, p_q2, N);
    k_bnfin<<<1, 64>>>(p_s2, p_q2, g2, be2, p_al2, p_bt2, 64, 1.f / (float)N);

    // --- Head: BN2+relu+dot fused ---
    k_final<<<(N + 7) / 8, 256>>>(W3, b3, out, N);
}

// round 8
// speedup vs baseline: 1.4910x; 1.2874x over previous
#include <cuda_runtime.h>
#include <cuda_fp16.h>
#include <cstdint>

// ---------------------------------------------------------------------------
// Problem constants (fixed by the dataset)
// ---------------------------------------------------------------------------
#define NMAX 50000
#define EMAX 800000

// ---------------------------------------------------------------------------
// Scratch (static __device__ arrays — no allocation allowed)
// ---------------------------------------------------------------------------
__device__ int   g_count[NMAX];
__device__ int   g_rowptr[NMAX + 1];
__device__ int   g_cursor[NMAX];
__device__ int   g_esrc[EMAX];
__device__ float g_mean[(size_t)NMAX * 128];  // layer1 uses [N,100], layer2 [N,128]
__device__ float g_t1[(size_t)NMAX * 128];    // pre-BN MLP1 activations
__device__ float g_t2[(size_t)NMAX * 64];     // pre-BN MLP2 activations
__device__ float g_s1[128], g_q1[128], g_s2[64], g_q2[64];     // BN sums / sumsq
__device__ float g_al1[128], g_bt1[128], g_al2[64], g_bt2[64]; // BN affine

// ---------------------------------------------------------------------------
// fp16 split helpers (Markidis split: v = hi + lo, products exact in fp32 acc)
// ---------------------------------------------------------------------------
__device__ __forceinline__ void split_store(__half* hi_p, __half* lo_p,
                                            float v0, float v1) {
    __half h0 = __float2half_rn(v0), h1 = __float2half_rn(v1);
    __half l0 = __float2half_rn(v0 - __half2float(h0));
    __half l1 = __float2half_rn(v1 - __half2float(h1));
    *(__half2*)hi_p = __halves2half2(h0, h1);
    *(__half2*)lo_p = __halves2half2(l0, l1);
}
__device__ __forceinline__ uint32_t ld32(const __half* p) {
    return *(const uint32_t*)p;
}
__device__ __forceinline__ void mma_f16(float* c,
                                        uint32_t a0, uint32_t a1, uint32_t a2, uint32_t a3,
                                        uint32_t b0, uint32_t b1) {
    asm volatile(
        "mma.sync.aligned.m16n8k16.row.col.f32.f16.f16.f32 "
        "{%0,%1,%2,%3}, {%4,%5,%6,%7}, {%8,%9}, {%0,%1,%2,%3};"
        : "+f"(c[0]), "+f"(c[1]), "+f"(c[2]), "+f"(c[3])
        : "r"(a0), "r"(a1), "r"(a2), "r"(a3), "r"(b0), "r"(b1));
}

// ---------------------------------------------------------------------------
// CSR build: zero -> histogram -> scan -> scatter
// ---------------------------------------------------------------------------
__global__ void k_zero(int n) {
    int i = blockIdx.x * blockDim.x + threadIdx.x;
    if (i < n) g_count[i] = 0;
    if (i < 128) { g_s1[i] = 0.f; g_q1[i] = 0.f; }
    if (i < 64)  { g_s2[i] = 0.f; g_q2[i] = 0.f; }
}

__global__ void k_hist(const int* __restrict__ dst, int E) {
    int i = blockIdx.x * blockDim.x + threadIdx.x;
    if (i < E) atomicAdd(&g_count[dst[i]], 1);
}

__global__ void k_scan(int N) {
    __shared__ int sums[1024];
    int t = threadIdx.x;
    int chunk = (N + 1023) >> 10;
    int b = t * chunk;
    int e = b + chunk; if (e > N) e = N;
    int s = 0;
    for (int i = b; i < e; i++) s += g_count[i];
    sums[t] = s;
    __syncthreads();
    int own = s;
    for (int off = 1; off < 1024; off <<= 1) {
        int v = (t >= off) ? sums[t - off] : 0;
        __syncthreads();
        sums[t] += v;
        __syncthreads();
    }
    int pre = sums[t] - own;  // exclusive prefix
    for (int i = b; i < e; i++) {
        g_rowptr[i] = pre;
        g_cursor[i] = pre;
        pre += g_count[i];
    }
    if (t == 1023) g_rowptr[N] = sums[1023];
}

__global__ void k_scatter(const int* __restrict__ src, const int* __restrict__ dst, int E) {
    int i = blockIdx.x * blockDim.x + threadIdx.x;
    if (i < E) {
        int d = dst[i];
        int p = atomicAdd(&g_cursor[d], 1);
        g_esrc[p] = src[i];
    }
}

// ---------------------------------------------------------------------------
// Mean aggregation: warp per node, gather via CSR, register accumulators.
// Unrolled x4 for memory-level parallelism (4 row-gathers in flight).
// ---------------------------------------------------------------------------
template <int F>
__global__ void k_aggregate(const float* __restrict__ feat, float* __restrict__ mout, int N) {
    int g = blockIdx.x * blockDim.x + threadIdx.x;
    int w = g >> 5;
    int lane = g & 31;
    if (w >= N) return;
    int s = g_rowptr[w], e = g_rowptr[w + 1];
    constexpr int Q = F / 4;
    bool act = (lane < Q);
    int col = lane * 4;
    float ax = 0.f, ay = 0.f, az = 0.f, aw = 0.f;
    int i = s;
    for (; i + 3 < e; i += 4) {
        int s0 = g_esrc[i], s1 = g_esrc[i + 1], s2 = g_esrc[i + 2], s3 = g_esrc[i + 3];
        if (act) {
            float4 v0 = *(const float4*)&feat[(size_t)s0 * F + col];
            float4 v1 = *(const float4*)&feat[(size_t)s1 * F + col];
            float4 v2 = *(const float4*)&feat[(size_t)s2 * F + col];
            float4 v3 = *(const float4*)&feat[(size_t)s3 * F + col];
            ax += v0.x + v1.x + v2.x + v3.x;
            ay += v0.y + v1.y + v2.y + v3.y;
            az += v0.z + v1.z + v2.z + v3.z;
            aw += v0.w + v1.w + v2.w + v3.w;
        }
    }
    for (; i < e; i++) {
        int s0 = g_esrc[i];
        if (act) {
            float4 v = *(const float4*)&feat[(size_t)s0 * F + col];
            ax += v.x; ay += v.y; az += v.z; aw += v.w;
        }
    }
    if (act) {
        float inv = (e > s) ? 1.f / (float)(e - s) : 0.f;  // deg=0 -> mean=0
        float4 m = make_float4(ax * inv, ay * inv, az * inv, aw * inv);
        *(float4*)&mout[(size_t)w * F + col] = m;
    }
}

// ---------------------------------------------------------------------------
// Fused tensor-core GEMM, split-FP16 (hi/lo -> near-fp32 precision):
//   out[N, COLS] = epi( [A1 | A2] @ [Wa ; Wb] + bias )
//   EPI 1 (RELU):  relu store (SAGE layers, fused dual-source A)
//   EPI 2 (STATS): raw store + per-column sum/sumsq accumulation (pre-BN MLP)
//   AMODE 2: A1 staged as relu(A1*alpha[k]+beta[k]) (BN-apply fusion, mlp2)
// Block 256 threads (8 warps = 2 row-groups x 4 col-groups), tile 64 x COLS.
// W resident in SMEM as fp16 hi/lo [COLS][SAh]; A staged per tile [64][SAh].
// SAh % 64 == 8 -> all fragment LDS.32 conflict-free (word = 4*gid+tig mod 32).
// Per k16-step: 3 MMAs (lo*hi, hi*lo, hi*hi).
// ---------------------------------------------------------------------------
template <int KA, int KB, int COLS, int AMODE, int EPI>
__global__ void __launch_bounds__(256)
k_gemm(const float* __restrict__ A1, const float* __restrict__ A2,
       const float* __restrict__ alpha, const float* __restrict__ beta,
       const float* __restrict__ Wa, const float* __restrict__ Wb,
       const float* __restrict__ bias,
       float* __restrict__ outp,
       float* __restrict__ statS, float* __restrict__ statQ,
       int N) {
    constexpr int K   = KA + KB;                       // even (100/128 parts)
    constexpr int KP  = ((K + 15) / 16) * 16;          // padded K (mult of 16)
    constexpr int KP2 = KP / 2;
    constexpr int SAh = ((KP - 8 + 63) / 64) * 64 + 8; // stride: %64 == 8
    constexpr int BM  = 64;
    constexpr int WCOLS = COLS / 4;   // warp column span (32 or 16)
    constexpr int NT = WCOLS / 8;     // n-tiles per warp
    constexpr int MT = 2;             // m-tiles per warp (32 rows)

    extern __shared__ __half sm_h[];
    __half* Wt_hi = sm_h;                    // [COLS][SAh]
    __half* Wt_lo = Wt_hi + COLS * SAh;
    __half* As_hi = Wt_lo + COLS * SAh;      // [BM][SAh]
    __half* As_lo = As_hi + BM * SAh;

    int tid = threadIdx.x;
    int lane = tid & 31, wid = tid >> 5;
    int wr = wid & 1, wc = wid >> 1;        // row-group {0,1}, col-group {0..3}
    int gid = lane >> 2, tig = lane & 3;    // mma fragment coords

    // Stage W once (transposed [col][k], hi/lo split)
    for (int i = tid; i < COLS * KP2; i += 256) {
        int c = i / KP2, k = (i % KP2) * 2;
        float v0 = 0.f, v1 = 0.f;
        if (k < KA) {
            v0 = Wa[k * COLS + c];
            v1 = Wa[(k + 1) * COLS + c];
        } else if (KB > 0 && k < K) {
            v0 = Wb[(k - KA) * COLS + c];
            v1 = Wb[(k - KA + 1) * COLS + c];
        }
        split_store(Wt_hi + c * SAh + k, Wt_lo + c * SAh + k, v0, v1);
    }

    // Bias cache (per-thread column pairs)
    float bs0[NT], bs1[NT];
#pragma unroll
    for (int nt = 0; nt < NT; nt++) {
        int c = wc * WCOLS + nt * 8 + 2 * tig;
        bs0[nt] = bias[c];
        bs1[nt] = bias[c + 1];
    }

    float sS[NT * 2], sQ[NT * 2];
#pragma unroll
    for (int j = 0; j < NT * 2; j++) { sS[j] = 0.f; sQ[j] = 0.f; }

    for (int t0 = blockIdx.x * BM; t0 < N; t0 += gridDim.x * BM) {
        __syncthreads();  // protect As from previous tile's readers
        // Stage A tile (hi/lo, half2 stores, coalesced global reads)
        for (int i = tid; i < BM * KP2; i += 256) {
            int r = i / KP2, k = (i % KP2) * 2;
            int row = t0 + r;
            float v0 = 0.f, v1 = 0.f;
            if (row < N) {
                if (k < KA) {
                    v0 = A1[(size_t)row * KA + k];
                    v1 = A1[(size_t)row * KA + k + 1];
                    if (AMODE == 2) {
                        v0 = fmaxf(fmaf(v0, alpha[k], beta[k]), 0.f);
                        v1 = fmaxf(fmaf(v1, alpha[k + 1], beta[k + 1]), 0.f);
                    }
                } else if (KB > 0 && k < K) {
                    v0 = A2[(size_t)row * KB + (k - KA)];
                    v1 = A2[(size_t)row * KB + (k - KA) + 1];
                }
            }
            split_store(As_hi + r * SAh + k, As_lo + r * SAh + k, v0, v1);
        }
        __syncthreads();

        float acc[MT][NT][4];
#pragma unroll
        for (int mt = 0; mt < MT; mt++)
#pragma unroll
            for (int nt = 0; nt < NT; nt++)
#pragma unroll
                for (int j = 0; j < 4; j++) acc[mt][nt][j] = 0.f;

#pragma unroll 2
        for (int k0 = 0; k0 < KP; k0 += 16) {
            uint32_t ah[MT][4], al[MT][4];
#pragma unroll
            for (int mt = 0; mt < MT; mt++) {
                const __half* ph = As_hi + (wr * 32 + mt * 16 + gid) * SAh + k0 + 2 * tig;
                const __half* pl = As_lo + (wr * 32 + mt * 16 + gid) * SAh + k0 + 2 * tig;
                ah[mt][0] = ld32(ph);              al[mt][0] = ld32(pl);
                ah[mt][1] = ld32(ph + 8 * SAh);    al[mt][1] = ld32(pl + 8 * SAh);
                ah[mt][2] = ld32(ph + 8);          al[mt][2] = ld32(pl + 8);
                ah[mt][3] = ld32(ph + 8 * SAh + 8);al[mt][3] = ld32(pl + 8 * SAh + 8);
            }
#pragma unroll
            for (int nt = 0; nt < NT; nt++) {
                const __half* qh = Wt_hi + (wc * WCOLS + nt * 8 + gid) * SAh + k0 + 2 * tig;
                const __half* ql = Wt_lo + (wc * WCOLS + nt * 8 + gid) * SAh + k0 + 2 * tig;
                uint32_t bh0 = ld32(qh), bh1 = ld32(qh + 8);
                uint32_t bl0 = ld32(ql), bl1 = ld32(ql + 8);
#pragma unroll
                for (int mt = 0; mt < MT; mt++) {
                    // corrections first, main term last
                    mma_f16(acc[mt][nt], al[mt][0], al[mt][1], al[mt][2], al[mt][3], bh0, bh1);
                    mma_f16(acc[mt][nt], ah[mt][0], ah[mt][1], ah[mt][2], ah[mt][3], bl0, bl1);
                    mma_f16(acc[mt][nt], ah[mt][0], ah[mt][1], ah[mt][2], ah[mt][3], bh0, bh1);
                }
            }
        }

        // Epilogue
#pragma unroll
        for (int mt = 0; mt < MT; mt++) {
            int r0 = t0 + wr * 32 + mt * 16 + gid;  // c0/c1 row
            int r1 = r0 + 8;                        // c2/c3 row
#pragma unroll
            for (int nt = 0; nt < NT; nt++) {
                int col = wc * WCOLS + nt * 8 + 2 * tig;
                float o0 = acc[mt][nt][0] + bs0[nt];
                float o1 = acc[mt][nt][1] + bs1[nt];
                float o2 = acc[mt][nt][2] + bs0[nt];
                float o3 = acc[mt][nt][3] + bs1[nt];
                if (EPI == 1) {
                    o0 = fmaxf(o0, 0.f); o1 = fmaxf(o1, 0.f);
                    o2 = fmaxf(o2, 0.f); o3 = fmaxf(o3, 0.f);
                }
                if (r0 < N) {
                    if (EPI == 2) {
                        sS[nt * 2]     += o0; sQ[nt * 2]     += o0 * o0;
                        sS[nt * 2 + 1] += o1; sQ[nt * 2 + 1] += o1 * o1;
                    }
                    *(float2*)&outp[(size_t)r0 * COLS + col] = make_float2(o0, o1);
                }
                if (r1 < N) {
                    if (EPI == 2) {
                        sS[nt * 2]     += o2; sQ[nt * 2]     += o2 * o2;
                        sS[nt * 2 + 1] += o3; sQ[nt * 2 + 1] += o3 * o3;
                    }
                    *(float2*)&outp[(size_t)r1 * COLS + col] = make_float2(o2, o3);
                }
            }
        }
    }

    if (EPI == 2) {
        // Lanes sharing a column are {tig, tig+4, ..., tig+28}: xor-reduce 4,8,16
#pragma unroll
        for (int j = 0; j < NT * 2; j++) {
            float s = sS[j], q = sQ[j];
#pragma unroll
            for (int o = 4; o < 32; o <<= 1) {
                s += __shfl_xor_sync(0xffffffffu, s, o);
                q += __shfl_xor_sync(0xffffffffu, q, o);
            }
            if (gid == 0) {
                int col = wc * WCOLS + (j >> 1) * 8 + 2 * tig + (j & 1);
                atomicAdd(&statS[col], s);
                atomicAdd(&statQ[col], q);
            }
        }
    }
}

// ---------------------------------------------------------------------------
// BN finalize: alpha = gamma * rsqrt(var + eps), beta' = beta - mean*alpha
// ---------------------------------------------------------------------------
__global__ void k_bnfin(const float* __restrict__ s, const float* __restrict__ q,
                        const float* __restrict__ gam, const float* __restrict__ bet,
                        float* __restrict__ al, float* __restrict__ bt,
                        int C, float invN) {
    int c = threadIdx.x;
    if (c < C) {
        float m = s[c] * invN;
        float v = q[c] * invN - m * m;
        float a = gam[c] * rsqrtf(v + 1e-5f);
        al[c] = a;
        bt[c] = bet[c] - m * a;
    }
}

// ---------------------------------------------------------------------------
// Final head: out[i] = relu(BN2(t2[i])) . W3 + b3   (warp per node)
// ---------------------------------------------------------------------------
__global__ void k_final(const float* __restrict__ W3, const float* __restrict__ b3,
                        float* __restrict__ out, int N) {
    int g = blockIdx.x * blockDim.x + threadIdx.x;
    int w = g >> 5;
    int lane = g & 31;
    if (w >= N) return;
    float ta = g_t2[(size_t)w * 64 + lane];
    float tb = g_t2[(size_t)w * 64 + 32 + lane];
    float za = fmaxf(ta * g_al2[lane] + g_bt2[lane], 0.f);
    float zb = fmaxf(tb * g_al2[lane + 32] + g_bt2[lane + 32], 0.f);
    float p = za * W3[lane] + zb * W3[lane + 32];
#pragma unroll
    for (int o = 16; o > 0; o >>= 1) p += __shfl_xor_sync(0xffffffffu, p, o);
    if (lane == 0) out[w] = p + b3[0];
}

// ---------------------------------------------------------------------------
// Host launcher
// ---------------------------------------------------------------------------
extern "C" void kernel_launch(void* const* d_in, const int* in_sizes, int n_in,
                              void* d_out, int out_size) {
    const float* x   = (const float*)d_in[0];
    const int*   ei  = (const int*)d_in[1];
    const float* Wl1 = (const float*)d_in[2];
    const float* bl1 = (const float*)d_in[3];
    const float* Wr1 = (const float*)d_in[4];
    const float* Wl2 = (const float*)d_in[5];
    const float* bl2 = (const float*)d_in[6];
    const float* Wr2 = (const float*)d_in[7];
    const float* W1  = (const float*)d_in[8];
    const float* b1  = (const float*)d_in[9];
    const float* g1  = (const float*)d_in[10];
    const float* be1 = (const float*)d_in[11];
    const float* W2  = (const float*)d_in[12];
    const float* b2  = (const float*)d_in[13];
    const float* g2  = (const float*)d_in[14];
    const float* be2 = (const float*)d_in[15];
    const float* W3  = (const float*)d_in[16];
    const float* b3  = (const float*)d_in[17];

    int N = in_sizes[0] / 100;
    int E = in_sizes[1] / 2;
    const int* src = ei;
    const int* dst = ei + E;

    float* out = (float*)d_out;
    float* h1  = out + N;
    float* h2  = h1 + (size_t)N * 128;

    // Scratch symbol addresses
    float *p_mean, *p_t1, *p_t2, *p_s1, *p_q1, *p_s2, *p_q2, *p_al1, *p_bt1, *p_al2, *p_bt2;
    cudaGetSymbolAddress((void**)&p_mean, g_mean);
    cudaGetSymbolAddress((void**)&p_t1, g_t1);
    cudaGetSymbolAddress((void**)&p_t2, g_t2);
    cudaGetSymbolAddress((void**)&p_s1, g_s1);
    cudaGetSymbolAddress((void**)&p_q1, g_q1);
    cudaGetSymbolAddress((void**)&p_s2, g_s2);
    cudaGetSymbolAddress((void**)&p_q2, g_q2);
    cudaGetSymbolAddress((void**)&p_al1, g_al1);
    cudaGetSymbolAddress((void**)&p_bt1, g_bt1);
    cudaGetSymbolAddress((void**)&p_al2, g_al2);
    cudaGetSymbolAddress((void**)&p_bt2, g_bt2);

    // Dynamic SMEM: (2*COLS + 2*64) * SAh * 2 bytes
    // sage1: K=200 -> KP=208, SAh=264 : 384*264*2 = 202752
    // sage2: K=256 -> KP=256, SAh=264 : 202752
    // mlp1 : K=128 -> KP=128, SAh=136 : 384*136*2 = 104448
    // mlp2 : COLS=64               : 256*136*2 =  69632
    const int SM_SAGE = 384 * 264 * 2;
    const int SM_M1   = 384 * 136 * 2;
    const int SM_M2   = 256 * 136 * 2;

    cudaFuncSetAttribute(k_gemm<100, 100, 128, 0, 1>,
                         cudaFuncAttributeMaxDynamicSharedMemorySize, SM_SAGE);
    cudaFuncSetAttribute(k_gemm<128, 128, 128, 0, 1>,
                         cudaFuncAttributeMaxDynamicSharedMemorySize, SM_SAGE);
    cudaFuncSetAttribute(k_gemm<128, 0, 128, 0, 2>,
                         cudaFuncAttributeMaxDynamicSharedMemorySize, SM_M1);
    cudaFuncSetAttribute(k_gemm<128, 0, 64, 2, 2>,
                         cudaFuncAttributeMaxDynamicSharedMemorySize, SM_M2);

    // --- CSR build (once; reused by both SAGE layers) ---
    k_zero<<<(N + 255) / 256, 256>>>(N);
    k_hist<<<(E + 255) / 256, 256>>>(dst, E);
    k_scan<<<1, 1024>>>(N);
    k_scatter<<<(E + 255) / 256, 256>>>(src, dst, E);

    // --- SAGE layer 1: h1 = relu([mean | x] @ [Wl1 ; Wr1] + bl1) ---
    k_aggregate<100><<<(N + 7) / 8, 256>>>(x, p_mean, N);
    k_gemm<100, 100, 128, 0, 1><<<148, 256, SM_SAGE>>>(
        p_mean, x, nullptr, nullptr, Wl1, Wr1, bl1, h1, nullptr, nullptr, N);

    // --- SAGE layer 2: h2 = relu([mean(h1) | h1] @ [Wl2 ; Wr2] + bl2) ---
    k_aggregate<128><<<(N + 7) / 8, 256>>>(h1, p_mean, N);
    k_gemm<128, 128, 128, 0, 1><<<148, 256, SM_SAGE>>>(
        p_mean, h1, nullptr, nullptr, Wl2, Wr2, bl2, h2, nullptr, nullptr, N);

    // --- MLP layer 1 (pre-BN t1 + column stats) ---
    k_gemm<128, 0, 128, 0, 2><<<296, 256, SM_M1>>>(
        h2, nullptr, nullptr, nullptr, W1, nullptr, b1, p_t1, p_s1, p_q1, N);
    k_bnfin<<<1, 128>>>(p_s1, p_q1, g1, be1, p_al1, p_bt1, 128, 1.f / (float)N);

    // --- MLP layer 2 (BN1+relu fused into A staging; pre-BN t2 + stats) ---
    k_gemm<128, 0, 64, 2, 2><<<444, 256, SM_M2>>>(
        p_t1, nullptr, p_al1, p_bt1, W2, nullptr, b2, p_t2, p_s2, p_q2, N);
    k_bnfin<<<1, 64>>>(p_s2, p_q2, g2, be2, p_al2, p_bt2, 64, 1.f / (float)N);

    // --- Head: BN2+relu+dot fused ---
    k_final<<<(N + 7) / 8, 256>>>(W3, b3, out, N);
}

// round 12
// speedup vs baseline: 1.6149x; 1.0831x over previous
// rev: R10 resubmit of ldmatrix kernel (R9 hit container init flake)
#include <cuda_runtime.h>
#include <cuda_fp16.h>
#include <cstdint>

// ---------------------------------------------------------------------------
// Problem constants (fixed by the dataset)
// ---------------------------------------------------------------------------
#define NMAX 50000
#define EMAX 800000

// ---------------------------------------------------------------------------
// Scratch (static __device__ arrays — no allocation allowed)
// ---------------------------------------------------------------------------
__device__ int   g_count[NMAX];
__device__ int   g_rowptr[NMAX + 1];
__device__ int   g_cursor[NMAX];
__device__ int   g_esrc[EMAX];
__device__ float g_mean[(size_t)NMAX * 128];  // layer1 uses [N,100], layer2 [N,128]
__device__ float g_t1[(size_t)NMAX * 128];    // pre-BN MLP1 activations
__device__ float g_t2[(size_t)NMAX * 64];    // pre-BN MLP2 activations
__device__ float g_s1[128], g_q1[128], g_s2[64], g_q2[64];     // BN sums / sumsq
__device__ float g_al1[128], g_bt1[128], g_al2[64], g_bt2[64]; // BN affine

// ---------------------------------------------------------------------------
// fp16 split helpers (Markidis split: v = hi + lo, products exact in fp32 acc)
// ---------------------------------------------------------------------------
__device__ __forceinline__ void split_store(__half* hi_p, __half* lo_p,
                                            float v0, float v1) {
    __half h0 = __float2half_rn(v0), h1 = __float2half_rn(v1);
    __half l0 = __float2half_rn(v0 - __half2float(h0));
    __half l1 = __float2half_rn(v1 - __half2float(h1));
    *(__half2*)hi_p = __halves2half2(h0, h1);
    *(__half2*)lo_p = __halves2half2(l0, l1);
}
__device__ __forceinline__ uint32_t sm_u32(const void* p) {
    return (uint32_t)__cvta_generic_to_shared(p);
}
__device__ __forceinline__ void ldsm_x4(uint32_t& r0, uint32_t& r1,
                                        uint32_t& r2, uint32_t& r3, uint32_t addr) {
    asm volatile("ldmatrix.sync.aligned.m8n8.x4.shared.b16 {%0,%1,%2,%3}, [%4];"
                 : "=r"(r0), "=r"(r1), "=r"(r2), "=r"(r3) : "r"(addr));
}
__device__ __forceinline__ void mma_f16(float* c,
                                        uint32_t a0, uint32_t a1, uint32_t a2, uint32_t a3,
                                        uint32_t b0, uint32_t b1) {
    asm volatile(
        "mma.sync.aligned.m16n8k16.row.col.f32.f16.f16.f32 "
        "{%0,%1,%2,%3}, {%4,%5,%6,%7}, {%8,%9}, {%0,%1,%2,%3};"
        : "+f"(c[0]), "+f"(c[1]), "+f"(c[2]), "+f"(c[3])
        : "r"(a0), "r"(a1), "r"(a2), "r"(a3), "r"(b0), "r"(b1));
}

// ---------------------------------------------------------------------------
// CSR build: zero -> histogram -> scan -> scatter
// ---------------------------------------------------------------------------
__global__ void k_zero(int n) {
    int i = blockIdx.x * blockDim.x + threadIdx.x;
    if (i < n) g_count[i] = 0;
    if (i < 128) { g_s1[i] = 0.f; g_q1[i] = 0.f; }
    if (i < 64)  { g_s2[i] = 0.f; g_q2[i] = 0.f; }
}

__global__ void k_hist(const int* __restrict__ dst, int E) {
    int i = blockIdx.x * blockDim.x + threadIdx.x;
    if (i < E) atomicAdd(&g_count[dst[i]], 1);
}

__global__ void k_scan(int N) {
    __shared__ int sums[1024];
    int t = threadIdx.x;
    int chunk = (N + 1023) >> 10;
    int b = t * chunk;
    int e = b + chunk; if (e > N) e = N;
    int s = 0;
    for (int i = b; i < e; i++) s += g_count[i];
    sums[t] = s;
    __syncthreads();
    int own = s;
    for (int off = 1; off < 1024; off <<= 1) {
        int v = (t >= off) ? sums[t - off] : 0;
        __syncthreads();
        sums[t] += v;
        __syncthreads();
    }
    int pre = sums[t] - own;  // exclusive prefix
    for (int i = b; i < e; i++) {
        g_rowptr[i] = pre;
        g_cursor[i] = pre;
        pre += g_count[i];
    }
    if (t == 1023) g_rowptr[N] = sums[1023];
}

__global__ void k_scatter(const int* __restrict__ src, const int* __restrict__ dst, int E) {
    int i = blockIdx.x * blockDim.x + threadIdx.x;
    if (i < E) {
        int d = dst[i];
        int p = atomicAdd(&g_cursor[d], 1);
        g_esrc[p] = src[i];
    }
}

// ---------------------------------------------------------------------------
// Mean aggregation: warp per node, gather via CSR, register accumulators.
// Unrolled x4 for memory-level parallelism (4 row-gathers in flight).
// ---------------------------------------------------------------------------
template <int F>
__global__ void k_aggregate(const float* __restrict__ feat, float* __restrict__ mout, int N) {
    int g = blockIdx.x * blockDim.x + threadIdx.x;
    int w = g >> 5;
    int lane = g & 31;
    if (w >= N) return;
    int s = g_rowptr[w], e = g_rowptr[w + 1];
    constexpr int Q = F / 4;
    bool act = (lane < Q);
    int col = lane * 4;
    float ax = 0.f, ay = 0.f, az = 0.f, aw = 0.f;
    int i = s;
    for (; i + 3 < e; i += 4) {
        int s0 = g_esrc[i], s1 = g_esrc[i + 1], s2 = g_esrc[i + 2], s3 = g_esrc[i + 3];
        if (act) {
            float4 v0 = *(const float4*)&feat[(size_t)s0 * F + col];
            float4 v1 = *(const float4*)&feat[(size_t)s1 * F + col];
            float4 v2 = *(const float4*)&feat[(size_t)s2 * F + col];
            float4 v3 = *(const float4*)&feat[(size_t)s3 * F + col];
            ax += v0.x + v1.x + v2.x + v3.x;
            ay += v0.y + v1.y + v2.y + v3.y;
            az += v0.z + v1.z + v2.z + v3.z;
            aw += v0.w + v1.w + v2.w + v3.w;
        }
    }
    for (; i < e; i++) {
        int s0 = g_esrc[i];
        if (act) {
            float4 v = *(const float4*)&feat[(size_t)s0 * F + col];
            ax += v.x; ay += v.y; az += v.z; aw += v.w;
        }
    }
    if (act) {
        float inv = (e > s) ? 1.f / (float)(e - s) : 0.f;  // deg=0 -> mean=0
        float4 m = make_float4(ax * inv, ay * inv, az * inv, aw * inv);
        *(float4*)&mout[(size_t)w * F + col] = m;
    }
}

// ---------------------------------------------------------------------------
// Fused tensor-core GEMM, split-FP16 (hi/lo -> near-fp32 precision):
//   out[N, COLS] = epi( [A1 | A2] @ [Wa ; Wb] + bias )
//   EPI 1 (RELU):  relu store (SAGE layers, fused dual-source A)
//   EPI 2 (STATS): raw store + per-column sum/sumsq accumulation (pre-BN MLP)
//   AMODE 2: A1 staged as relu(A1*alpha[k]+beta[k]) (BN-apply fusion, mlp2)
// Block 256 threads (8 warps = 2 row-groups x 4 col-groups), tile 64 x COLS.
// W resident in SMEM as fp16 hi/lo [COLS][SAh]; A staged per tile [64][SAh].
// SAh % 64 == 8 -> ldmatrix 8x8 tiles cover all 32 banks (conflict-free).
// Fragments loaded via ldmatrix.x4 (8 LDSM vs 32 LDS per k-step).
// Per k16-step: 3 MMAs (lo*hi, hi*lo, hi*hi).
// ---------------------------------------------------------------------------
template <int KA, int KB, int COLS, int AMODE, int EPI>
__global__ void __launch_bounds__(256)
k_gemm(const float* __restrict__ A1, const float* __restrict__ A2,
       const float* __restrict__ alpha, const float* __restrict__ beta,
       const float* __restrict__ Wa, const float* __restrict__ Wb,
       const float* __restrict__ bias,
       float* __restrict__ outp,
       float* __restrict__ statS, float* __restrict__ statQ,
       int N) {
    constexpr int K   = KA + KB;                       // even (100/128 parts)
    constexpr int KP  = ((K + 15) / 16) * 16;          // padded K (mult of 16)
    constexpr int KP2 = KP / 2;
    constexpr int SAh = ((KP - 8 + 63) / 64) * 64 + 8; // stride: %64 == 8
    constexpr int BM  = 64;
    constexpr int WCOLS = COLS / 4;   // warp column span (32 or 16)
    constexpr int NT = WCOLS / 8;     // n-tiles per warp (4 or 2)
    constexpr int NP = NT / 2;        // ldmatrix nt-pairs (2 or 1)
    constexpr int MT = 2;             // m-tiles per warp (32 rows)

    extern __shared__ __half sm_h[];
    __half* Wt_hi = sm_h;                    // [COLS][SAh]
    __half* Wt_lo = Wt_hi + COLS * SAh;
    __half* As_hi = Wt_lo + COLS * SAh;      // [BM][SAh]
    __half* As_lo = As_hi + BM * SAh;

    int tid = threadIdx.x;
    int lane = tid & 31, wid = tid >> 5;
    int wr = wid & 1, wc = wid >> 1;        // row-group {0,1}, col-group {0..3}
    int gid = lane >> 2, tig = lane & 3;    // mma fragment coords

    // Stage W once (transposed [col][k], hi/lo split). Coalesced: consecutive
    // threads read consecutive columns of the same two weight rows.
    for (int i = tid; i < COLS * KP2; i += 256) {
        int k2 = i / COLS, c = i % COLS;
        int k = k2 * 2;
        float v0 = 0.f, v1 = 0.f;
        if (k < KA) {
            v0 = Wa[k * COLS + c];
            v1 = Wa[(k + 1) * COLS + c];
        } else if (KB > 0 && k < K) {
            v0 = Wb[(k - KA) * COLS + c];
            v1 = Wb[(k - KA + 1) * COLS + c];
        }
        split_store(Wt_hi + c * SAh + k, Wt_lo + c * SAh + k, v0, v1);
    }

    // ldmatrix source addresses (byte, shared space), k0-independent parts.
    // A (x4): lanes 0-15 -> rows base+0..15 @ k+0 ; lanes 16-31 -> same rows @ k+8
    //   regs: r0=(r,k) r1=(r+8,k) r2=(r,k+8) r3=(r+8,k+8)
    uint32_t aHi[MT], aLo[MT];
#pragma unroll
    for (int mt = 0; mt < MT; mt++) {
        int row = wr * 32 + mt * 16 + (lane & 15);
        int off = row * SAh + (lane >> 4) * 8;
        aHi[mt] = sm_u32(As_hi + off);
        aLo[mt] = sm_u32(As_lo + off);
    }
    // B (x4): lanes 0-7: cols c0..c0+7 @k ; 8-15: same cols @k+8 ;
    //         16-23: cols +8 @k ; 24-31: cols +8 @k+8
    //   regs: r0=b0(nt even) r1=b1(nt even) r2=b0(nt odd) r3=b1(nt odd)
    uint32_t bHi[NP], bLo[NP];
#pragma unroll
    for (int p = 0; p < NP; p++) {
        int col = wc * WCOLS + p * 16 + ((lane >> 4) & 1) * 8 + (lane & 7);
        int off = col * SAh + ((lane >> 3) & 1) * 8;
        bHi[p] = sm_u32(Wt_hi + off);
        bLo[p] = sm_u32(Wt_lo + off);
    }

    // Bias cache (per-thread column pairs)
    float bs0[NT], bs1[NT];
#pragma unroll
    for (int nt = 0; nt < NT; nt++) {
        int c = wc * WCOLS + nt * 8 + 2 * tig;
        bs0[nt] = bias[c];
        bs1[nt] = bias[c + 1];
    }

    float sS[NT * 2], sQ[NT * 2];
#pragma unroll
    for (int j = 0; j < NT * 2; j++) { sS[j] = 0.f; sQ[j] = 0.f; }

    for (int t0 = blockIdx.x * BM; t0 < N; t0 += gridDim.x * BM) {
        __syncthreads();  // protect As from previous tile's readers
        // Stage A tile (hi/lo split; float2 global reads, coalesced along k)
        for (int i = tid; i < BM * KP2; i += 256) {
            int r = i / KP2, k = (i % KP2) * 2;
            int row = t0 + r;
            float v0 = 0.f, v1 = 0.f;
            if (row < N) {
                if (k < KA) {
                    float2 v = *(const float2*)&A1[(size_t)row * KA + k];
                    v0 = v.x; v1 = v.y;
                    if (AMODE == 2) {
                        v0 = fmaxf(fmaf(v0, alpha[k], beta[k]), 0.f);
                        v1 = fmaxf(fmaf(v1, alpha[k + 1], beta[k + 1]), 0.f);
                    }
                } else if (KB > 0 && k < K) {
                    float2 v = *(const float2*)&A2[(size_t)row * KB + (k - KA)];
                    v0 = v.x; v1 = v.y;
                }
            }
            split_store(As_hi + r * SAh + k, As_lo + r * SAh + k, v0, v1);
        }
        __syncthreads();

        float acc[MT][NT][4];
#pragma unroll
        for (int mt = 0; mt < MT; mt++)
#pragma unroll
            for (int nt = 0; nt < NT; nt++)
#pragma unroll
                for (int j = 0; j < 4; j++) acc[mt][nt][j] = 0.f;

#pragma unroll 2
        for (int k0 = 0; k0 < KP; k0 += 16) {
            uint32_t kb = k0 * 2;  // byte offset along k
            uint32_t ah[MT][4], al[MT][4];
#pragma unroll
            for (int mt = 0; mt < MT; mt++) {
                ldsm_x4(ah[mt][0], ah[mt][1], ah[mt][2], ah[mt][3], aHi[mt] + kb);
                ldsm_x4(al[mt][0], al[mt][1], al[mt][2], al[mt][3], aLo[mt] + kb);
            }
            uint32_t bh[NT][2], bl[NT][2];
#pragma unroll
            for (int p = 0; p < NP; p++) {
                ldsm_x4(bh[2 * p][0], bh[2 * p][1], bh[2 * p + 1][0], bh[2 * p + 1][1],
                        bHi[p] + kb);
                ldsm_x4(bl[2 * p][0], bl[2 * p][1], bl[2 * p + 1][0], bl[2 * p + 1][1],
                        bLo[p] + kb);
            }
#pragma unroll
            for (int nt = 0; nt < NT; nt++) {
#pragma unroll
                for (int mt = 0; mt < MT; mt++) {
                    // corrections first, main term last
                    mma_f16(acc[mt][nt], al[mt][0], al[mt][1], al[mt][2], al[mt][3],
                            bh[nt][0], bh[nt][1]);
                    mma_f16(acc[mt][nt], ah[mt][0], ah[mt][1], ah[mt][2], ah[mt][3],
                            bl[nt][0], bl[nt][1]);
                    mma_f16(acc[mt][nt], ah[mt][0], ah[mt][1], ah[mt][2], ah[mt][3],
                            bh[nt][0], bh[nt][1]);
                }
            }
        }

        // Epilogue
#pragma unroll
        for (int mt = 0; mt < MT; mt++) {
            int r0 = t0 + wr * 32 + mt * 16 + gid;  // c0/c1 row
            int r1 = r0 + 8;                        // c2/c3 row
#pragma unroll
            for (int nt = 0; nt < NT; nt++) {
                int col = wc * WCOLS + nt * 8 + 2 * tig;
                float o0 = acc[mt][nt][0] + bs0[nt];
                float o1 = acc[mt][nt][1] + bs1[nt];
                float o2 = acc[mt][nt][2] + bs0[nt];
                float o3 = acc[mt][nt][3] + bs1[nt];
                if (EPI == 1) {
                    o0 = fmaxf(o0, 0.f); o1 = fmaxf(o1, 0.f);
                    o2 = fmaxf(o2, 0.f); o3 = fmaxf(o3, 0.f);
                }
                if (r0 < N) {
                    if (EPI == 2) {
                        sS[nt * 2]     += o0; sQ[nt * 2]     += o0 * o0;
                        sS[nt * 2 + 1] += o1; sQ[nt * 2 + 1] += o1 * o1;
                    }
                    *(float2*)&outp[(size_t)r0 * COLS + col] = make_float2(o0, o1);
                }
                if (r1 < N) {
                    if (EPI == 2) {
                        sS[nt * 2]     += o2; sQ[nt * 2]     += o2 * o2;
                        sS[nt * 2 + 1] += o3; sQ[nt * 2 + 1] += o3 * o3;
                    }
                    *(float2*)&outp[(size_t)r1 * COLS + col] = make_float2(o2, o3);
                }
            }
        }
    }

    if (EPI == 2) {
        // Lanes sharing a column are {tig, tig+4, ..., tig+28}: xor-reduce 4,8,16
#pragma unroll
        for (int j = 0; j < NT * 2; j++) {
            float s = sS[j], q = sQ[j];
#pragma unroll
            for (int o = 4; o < 32; o <<= 1) {
                s += __shfl_xor_sync(0xffffffffu, s, o);
                q += __shfl_xor_sync(0xffffffffu, q, o);
            }
            if (gid == 0) {
                int col = wc * WCOLS + (j >> 1) * 8 + 2 * tig + (j & 1);
                atomicAdd(&statS[col], s);
                atomicAdd(&statQ[col], q);
            }
        }
    }
}

// ---------------------------------------------------------------------------
// BN finalize: alpha = gamma * rsqrt(var + eps), beta' = beta - mean*alpha
// ---------------------------------------------------------------------------
__global__ void k_bnfin(const float* __restrict__ s, const float* __restrict__ q,
                        const float* __restrict__ gam, const float* __restrict__ bet,
                        float* __restrict__ al, float* __restrict__ bt,
                        int C, float invN) {
    int c = threadIdx.x;
    if (c < C) {
        float m = s[c] * invN;
        float v = q[c] * invN - m * m;
        float a = gam[c] * rsqrtf(v + 1e-5f);
        al[c] = a;
        bt[c] = bet[c] - m * a;
    }
}

// ---------------------------------------------------------------------------
// Final head: out[i] = relu(BN2(t2[i])) . W3 + b3   (warp per node)
// ---------------------------------------------------------------------------
__global__ void k_final(const float* __restrict__ W3, const float* __restrict__ b3,
                        float* __restrict__ out, int N) {
    int g = blockIdx.x * blockDim.x + threadIdx.x;
    int w = g >> 5;
    int lane = g & 31;
    if (w >= N) return;
    float ta = g_t2[(size_t)w * 64 + lane];
    float tb = g_t2[(size_t)w * 64 + 32 + lane];
    float za = fmaxf(ta * g_al2[lane] + g_bt2[lane], 0.f);
    float zb = fmaxf(tb * g_al2[lane + 32] + g_bt2[lane + 32], 0.f);
    float p = za * W3[lane] + zb * W3[lane + 32];
#pragma unroll
    for (int o = 16; o > 0; o >>= 1) p += __shfl_xor_sync(0xffffffffu, p, o);
    if (lane == 0) out[w] = p + b3[0];
}

// ---------------------------------------------------------------------------
// Host launcher
// ---------------------------------------------------------------------------
extern "C" void kernel_launch(void* const* d_in, const int* in_sizes, int n_in,
                              void* d_out, int out_size) {
    const float* x   = (const float*)d_in[0];
    const int*   ei  = (const int*)d_in[1];
    const float* Wl1 = (const float*)d_in[2];
    const float* bl1 = (const float*)d_in[3];
    const float* Wr1 = (const float*)d_in[4];
    const float* Wl2 = (const float*)d_in[5];
    const float* bl2 = (const float*)d_in[6];
    const float* Wr2 = (const float*)d_in[7];
    const float* W1  = (const float*)d_in[8];
    const float* b1  = (const float*)d_in[9];
    const float* g1  = (const float*)d_in[10];
    const float* be1 = (const float*)d_in[11];
    const float* W2  = (const float*)d_in[12];
    const float* b2  = (const float*)d_in[13];
    const float* g2  = (const float*)d_in[14];
    const float* be2 = (const float*)d_in[15];
    const float* W3  = (const float*)d_in[16];
    const float* b3  = (const float*)d_in[17];

    int N = in_sizes[0] / 100;
    int E = in_sizes[1] / 2;
    const int* src = ei;
    const int* dst = ei + E;

    float* out = (float*)d_out;
    float* h1  = out + N;
    float* h2  = h1 + (size_t)N * 128;

    // Scratch symbol addresses
    float *p_mean, *p_t1, *p_t2, *p_s1, *p_q1, *p_s2, *p_q2, *p_al1, *p_bt1, *p_al2, *p_bt2;
    cudaGetSymbolAddress((void**)&p_mean, g_mean);
    cudaGetSymbolAddress((void**)&p_t1, g_t1);
    cudaGetSymbolAddress((void**)&p_t2, g_t2);
    cudaGetSymbolAddress((void**)&p_s1, g_s1);
    cudaGetSymbolAddress((void**)&p_q1, g_q1);
    cudaGetSymbolAddress((void**)&p_s2, g_s2);
    cudaGetSymbolAddress((void**)&p_q2, g_q2);
    cudaGetSymbolAddress((void**)&p_al1, g_al1);
    cudaGetSymbolAddress((void**)&p_bt1, g_bt1);
    cudaGetSymbolAddress((void**)&p_al2, g_al2);
    cudaGetSymbolAddress((void**)&p_bt2, g_bt2);

    // Dynamic SMEM: (2*COLS + 2*64) * SAh * 2 bytes
    const int SM_SAGE = 384 * 264 * 2;  // K=200/256 -> SAh=264 : 202752
    const int SM_M1   = 384 * 136 * 2;  // K=128 -> SAh=136     : 104448
    const int SM_M2   = 256 * 136 * 2;  // COLS=64              :  69632

    cudaFuncSetAttribute(k_gemm<100, 100, 128, 0, 1>,
                         cudaFuncAttributeMaxDynamicSharedMemorySize, SM_SAGE);
    cudaFuncSetAttribute(k_gemm<128, 128, 128, 0, 1>,
                         cudaFuncAttributeMaxDynamicSharedMemorySize, SM_SAGE);
    cudaFuncSetAttribute(k_gemm<128, 0, 128, 0, 2>,
                         cudaFuncAttributeMaxDynamicSharedMemorySize, SM_M1);
    cudaFuncSetAttribute(k_gemm<128, 0, 64, 2, 2>,
                         cudaFuncAttributeMaxDynamicSharedMemorySize, SM_M2);

    // --- CSR build (once; reused by both SAGE layers) ---
    k_zero<<<(N + 255) / 256, 256>>>(N);
    k_hist<<<(E + 255) / 256, 256>>>(dst, E);
    k_scan<<<1, 1024>>>(N);
    k_scatter<<<(E + 255) / 256, 256>>>(src, dst, E);

    // --- SAGE layer 1: h1 = relu([mean | x] @ [Wl1 ; Wr1] + bl1) ---
    k_aggregate<100><<<(N + 7) / 8, 256>>>(x, p_mean, N);
    k_gemm<100, 100, 128, 0, 1><<<148, 256, SM_SAGE>>>(
        p_mean, x, nullptr, nullptr, Wl1, Wr1, bl1, h1, nullptr, nullptr, N);

    // --- SAGE layer 2: h2 = relu([mean(h1) | h1] @ [Wl2 ; Wr2] + bl2) ---
    k_aggregate<128><<<(N + 7) / 8, 256>>>(h1, p_mean, N);
    k_gemm<128, 128, 128, 0, 1><<<148, 256, SM_SAGE>>>(
        p_mean, h1, nullptr, nullptr, Wl2, Wr2, bl2, h2, nullptr, nullptr, N);

    // --- MLP layer 1 (pre-BN t1 + column stats) ---
    k_gemm<128, 0, 128, 0, 2><<<296, 256, SM_M1>>>(
        h2, nullptr, nullptr, nullptr, W1, nullptr, b1, p_t1, p_s1, p_q1, N);
    k_bnfin<<<1, 128>>>(p_s1, p_q1, g1, be1, p_al1, p_bt1, 128, 1.f / (float)N);

    // --- MLP layer 2 (BN1+relu fused into A staging; pre-BN t2 + stats) ---
    k_gemm<128, 0, 64, 2, 2><<<444, 256, SM_M2>>>(
        p_t1, nullptr, p_al1, p_bt1, W2, nullptr, b2, p_t2, p_s2, p_q2, N);
    k_bnfin<<<1, 64>>>(p_s2, p_q2, g2, be2, p_al2, p_bt2, 64, 1.f / (float)N);

    // --- Head: BN2+relu+dot fused ---
    k_final<<<(N + 7) / 8, 256>>>(W3, b3, out, N);
}

// round 13
// speedup vs baseline: 1.7552x; 1.0868x over previous
// rev: R13 — pre-split A operands into fp16 hi/lo planes; GEMM staging = pure copy
#include <cuda_runtime.h>
#include <cuda_fp16.h>
#include <cstdint>

// ---------------------------------------------------------------------------
// Problem constants (fixed by the dataset)
// ---------------------------------------------------------------------------
#define NMAX 50000
#define EMAX 800000
#define NPAD 50048   // NMAX rounded up to 64-row tile

// ---------------------------------------------------------------------------
// Scratch (static __device__ arrays — no allocation allowed)
// ---------------------------------------------------------------------------
__device__ int    g_count[NMAX];
__device__ int    g_rowptr[NMAX + 1];
__device__ int    g_cursor[NMAX];
__device__ int    g_esrc[EMAX];
__device__ __half g_ahi[(size_t)NPAD * 256];  // pre-split A operand, hi plane
__device__ __half g_alo[(size_t)NPAD * 256];  // pre-split A operand, lo plane
__device__ float  g_t1[(size_t)NMAX * 128];   // pre-BN MLP1 activations
__device__ float  g_t2[(size_t)NMAX * 64];    // pre-BN MLP2 activations
__device__ float  g_s1[128], g_q1[128], g_s2[64], g_q2[64];     // BN sums / sumsq
__device__ float  g_al1[128], g_bt1[128], g_al2[64], g_bt2[64]; // BN affine

// ---------------------------------------------------------------------------
// fp16 split helpers (Markidis split: v = hi + lo, products exact in fp32 acc)
// ---------------------------------------------------------------------------
__device__ __forceinline__ void split2(float v0, float v1, uint32_t& hi, uint32_t& lo) {
    __half2 h = __floats2half2_rn(v0, v1);
    float2 hf = __half22float2(h);
    __half2 l = __floats2half2_rn(v0 - hf.x, v1 - hf.y);
    hi = *(uint32_t*)&h;
    lo = *(uint32_t*)&l;
}
__device__ __forceinline__ void split_store(__half* hi_p, __half* lo_p,
                                            float v0, float v1) {
    uint32_t hi, lo;
    split2(v0, v1, hi, lo);
    *(uint32_t*)hi_p = hi;
    *(uint32_t*)lo_p = lo;
}
__device__ __forceinline__ uint32_t sm_u32(const void* p) {
    return (uint32_t)__cvta_generic_to_shared(p);
}
__device__ __forceinline__ void ldsm_x4(uint32_t& r0, uint32_t& r1,
                                        uint32_t& r2, uint32_t& r3, uint32_t addr) {
    asm volatile("ldmatrix.sync.aligned.m8n8.x4.shared.b16 {%0,%1,%2,%3}, [%4];"
                 : "=r"(r0), "=r"(r1), "=r"(r2), "=r"(r3) : "r"(addr));
}
__device__ __forceinline__ void mma_f16(float* c,
                                        uint32_t a0, uint32_t a1, uint32_t a2, uint32_t a3,
                                        uint32_t b0, uint32_t b1) {
    asm volatile(
        "mma.sync.aligned.m16n8k16.row.col.f32.f16.f16.f32 "
        "{%0,%1,%2,%3}, {%4,%5,%6,%7}, {%8,%9}, {%0,%1,%2,%3};"
        : "+f"(c[0]), "+f"(c[1]), "+f"(c[2]), "+f"(c[3])
        : "r"(a0), "r"(a1), "r"(a2), "r"(a3), "r"(b0), "r"(b1));
}

// ---------------------------------------------------------------------------
// CSR build: zero -> histogram -> scan -> scatter
// ---------------------------------------------------------------------------
__global__ void k_zero(int n) {
    int i = blockIdx.x * blockDim.x + threadIdx.x;
    if (i < n) g_count[i] = 0;
    if (i < 128) { g_s1[i] = 0.f; g_q1[i] = 0.f; }
    if (i < 64)  { g_s2[i] = 0.f; g_q2[i] = 0.f; }
}

__global__ void k_hist(const int* __restrict__ dst, int E) {
    int i = blockIdx.x * blockDim.x + threadIdx.x;
    if (i < E) atomicAdd(&g_count[dst[i]], 1);
}

__global__ void k_scan(int N) {
    __shared__ int sums[1024];
    int t = threadIdx.x;
    int chunk = (N + 1023) >> 10;
    int b = t * chunk;
    int e = b + chunk; if (e > N) e = N;
    int s = 0;
    for (int i = b; i < e; i++) s += g_count[i];
    sums[t] = s;
    __syncthreads();
    int own = s;
    for (int off = 1; off < 1024; off <<= 1) {
        int v = (t >= off) ? sums[t - off] : 0;
        __syncthreads();
        sums[t] += v;
        __syncthreads();
    }
    int pre = sums[t] - own;  // exclusive prefix
    for (int i = b; i < e; i++) {
        g_rowptr[i] = pre;
        g_cursor[i] = pre;
        pre += g_count[i];
    }
    if (t == 1023) g_rowptr[N] = sums[1023];
}

__global__ void k_scatter(const int* __restrict__ src, const int* __restrict__ dst, int E) {
    int i = blockIdx.x * blockDim.x + threadIdx.x;
    if (i < E) {
        int d = dst[i];
        int p = atomicAdd(&g_cursor[d], 1);
        g_esrc[p] = src[i];
    }
}

// ---------------------------------------------------------------------------
// Split passes: fp32 src -> fp16 hi/lo planes at [row*KP + KOFF + k].
// Memory-bound; conversion ALU hides under load/store latency.
// ---------------------------------------------------------------------------
// x: F=100 into KP=208 at KOFF=100, also zero-pads cols [200,208) every launch
// (pad bytes are clobbered by the stride-256 layout on prior graph replays).
__global__ void k_splitx(const float* __restrict__ x, int N) {
    int i = blockIdx.x * blockDim.x + threadIdx.x;
    int r = i / 54, k2 = i % 54;       // 54 half2 pairs cover cols 100..207
    if (r >= N) return;
    float v0 = 0.f, v1 = 0.f;
    if (k2 < 50) {
        float2 v = *(const float2*)&x[(size_t)r * 100 + 2 * k2];
        v0 = v.x; v1 = v.y;
    }
    size_t off = (size_t)r * 208 + 100 + 2 * k2;
    split_store(&g_ahi[off], &g_alo[off], v0, v1);
}

template <int F, int KOFF, int KP>
__global__ void k_split(const float* __restrict__ src, int N) {
    int i = blockIdx.x * blockDim.x + threadIdx.x;
    constexpr int F2 = F / 2;
    int r = i / F2, k2 = i % F2;
    if (r >= N) return;
    float2 v = *(const float2*)&src[(size_t)r * F + 2 * k2];
    size_t off = (size_t)r * KP + KOFF + 2 * k2;
    split_store(&g_ahi[off], &g_alo[off], v.x, v.y);
}

// bn-relu(t1) -> planes (KP=128): v = relu(v*alpha[k] + beta[k])
__global__ void k_splitbn(const float* __restrict__ src,
                          const float* __restrict__ alpha, const float* __restrict__ beta,
                          int N) {
    int i = blockIdx.x * blockDim.x + threadIdx.x;
    int r = i / 64, k2 = i % 64;
    if (r >= N) return;
    int k = 2 * k2;
    float2 v = *(const float2*)&src[(size_t)r * 128 + k];
    float v0 = fmaxf(fmaf(v.x, alpha[k], beta[k]), 0.f);
    float v1 = fmaxf(fmaf(v.y, alpha[k + 1], beta[k + 1]), 0.f);
    size_t off = (size_t)r * 128 + k;
    split_store(&g_ahi[off], &g_alo[off], v0, v1);
}

// ---------------------------------------------------------------------------
// Mean aggregation: warp per node, gather via CSR, register accumulators,
// x4 unroll for MLP. Epilogue writes the mean DIRECTLY as split hi/lo planes
// (cols [0,F) of the stride-KP concat buffer); conversions hidden under gather.
// ---------------------------------------------------------------------------
template <int F, int KP>
__global__ void k_aggregate(const float* __restrict__ feat, int N) {
    int g = blockIdx.x * blockDim.x + threadIdx.x;
    int w = g >> 5;
    int lane = g & 31;
    if (w >= N) return;
    int s = g_rowptr[w], e = g_rowptr[w + 1];
    constexpr int Q = F / 4;
    bool act = (lane < Q);
    int col = lane * 4;
    float ax = 0.f, ay = 0.f, az = 0.f, aw = 0.f;
    int i = s;
    for (; i + 3 < e; i += 4) {
        int s0 = g_esrc[i], s1 = g_esrc[i + 1], s2 = g_esrc[i + 2], s3 = g_esrc[i + 3];
        if (act) {
            float4 v0 = *(const float4*)&feat[(size_t)s0 * F + col];
            float4 v1 = *(const float4*)&feat[(size_t)s1 * F + col];
            float4 v2 = *(const float4*)&feat[(size_t)s2 * F + col];
            float4 v3 = *(const float4*)&feat[(size_t)s3 * F + col];
            ax += v0.x + v1.x + v2.x + v3.x;
            ay += v0.y + v1.y + v2.y + v3.y;
            az += v0.z + v1.z + v2.z + v3.z;
            aw += v0.w + v1.w + v2.w + v3.w;
        }
    }
    for (; i < e; i++) {
        int s0 = g_esrc[i];
        if (act) {
            float4 v = *(const float4*)&feat[(size_t)s0 * F + col];
            ax += v.x; ay += v.y; az += v.z; aw += v.w;
        }
    }
    if (act) {
        float inv = (e > s) ? 1.f / (float)(e - s) : 0.f;  // deg=0 -> mean=0
        uint32_t h0, l0, h1, l1;
        split2(ax * inv, ay * inv, h0, l0);
        split2(az * inv, aw * inv, h1, l1);
        size_t off = (size_t)w * KP + col;   // 8B aligned (col % 4 == 0)
        *(uint2*)&g_ahi[off] = make_uint2(h0, h1);
        *(uint2*)&g_alo[off] = make_uint2(l0, l1);
    }
}

// ---------------------------------------------------------------------------
// Fused tensor-core GEMM, split-FP16, PRE-SPLIT A:
//   out[N, COLS] = epi( A @ [Wa ; Wb] + bias ),  A read from g_ahi/g_alo
//   planes, [N][KP] fp16 each (KP mult of 16; rows N..NPAD never stored).
//   EPI 1 (RELU):  relu store (SAGE layers)
//   EPI 2 (STATS): raw store + per-column sum/sumsq accumulation (pre-BN MLP)
// A staging = pure uint4 copies (no conversion). W staged+split once per block.
// SAh % 64 == 8 -> ldmatrix 8x8 tiles conflict-free. 3 MMAs per k16-step.
// ---------------------------------------------------------------------------
template <int KP, int KWA, int KWB, int COLS, int EPI>
__global__ void __launch_bounds__(256)
k_gemm(const float* __restrict__ Wa, const float* __restrict__ Wb,
       const float* __restrict__ bias,
       float* __restrict__ outp,
       float* __restrict__ statS, float* __restrict__ statQ,
       int N) {
    constexpr int K   = KWA + KWB;                     // weight rows (<= KP)
    constexpr int KP2 = KP / 2;
    constexpr int SAh = ((KP - 8 + 63) / 64) * 64 + 8; // stride: %64 == 8
    constexpr int BM  = 64;
    constexpr int CHUNK = KP / 8;     // uint4 chunks per A row
    constexpr int WCOLS = COLS / 4;   // warp column span (32 or 16)
    constexpr int NT = WCOLS / 8;     // n-tiles per warp (4 or 2)
    constexpr int NP = NT / 2;        // ldmatrix nt-pairs (2 or 1)
    constexpr int MT = 2;             // m-tiles per warp (32 rows)

    extern __shared__ __half sm_h[];
    __half* Wt_hi = sm_h;                    // [COLS][SAh]
    __half* Wt_lo = Wt_hi + COLS * SAh;
    __half* As_hi = Wt_lo + COLS * SAh;      // [BM][SAh]
    __half* As_lo = As_hi + BM * SAh;

    int tid = threadIdx.x;
    int lane = tid & 31, wid = tid >> 5;
    int wr = wid & 1, wc = wid >> 1;        // row-group {0,1}, col-group {0..3}
    int gid = lane >> 2, tig = lane & 3;    // mma fragment coords

    // Stage W once (transposed [col][k], hi/lo split). Coalesced over columns.
    for (int i = tid; i < COLS * KP2; i += 256) {
        int k2 = i / COLS, c = i % COLS;
        int k = k2 * 2;
        float v0 = 0.f, v1 = 0.f;
        if (k < KWA) {
            v0 = Wa[k * COLS + c];
            v1 = Wa[(k + 1) * COLS + c];
        } else if (KWB > 0 && k < K) {
            v0 = Wb[(k - KWA) * COLS + c];
            v1 = Wb[(k - KWA + 1) * COLS + c];
        }
        split_store(Wt_hi + c * SAh + k, Wt_lo + c * SAh + k, v0, v1);
    }

    // ldmatrix source addresses (byte, shared space), k0-independent parts.
    uint32_t aHi[MT], aLo[MT];
#pragma unroll
    for (int mt = 0; mt < MT; mt++) {
        int row = wr * 32 + mt * 16 + (lane & 15);
        int off = row * SAh + (lane >> 4) * 8;
        aHi[mt] = sm_u32(As_hi + off);
        aLo[mt] = sm_u32(As_lo + off);
    }
    uint32_t bHi[NP], bLo[NP];
#pragma unroll
    for (int p = 0; p < NP; p++) {
        int col = wc * WCOLS + p * 16 + ((lane >> 4) & 1) * 8 + (lane & 7);
        int off = col * SAh + ((lane >> 3) & 1) * 8;
        bHi[p] = sm_u32(Wt_hi + off);
        bLo[p] = sm_u32(Wt_lo + off);
    }

    // Bias cache (per-thread column pairs)
    float bs0[NT], bs1[NT];
#pragma unroll
    for (int nt = 0; nt < NT; nt++) {
        int c = wc * WCOLS + nt * 8 + 2 * tig;
        bs0[nt] = bias[c];
        bs1[nt] = bias[c + 1];
    }

    float sS[NT * 2], sQ[NT * 2];
#pragma unroll
    for (int j = 0; j < NT * 2; j++) { sS[j] = 0.f; sQ[j] = 0.f; }

    for (int t0 = blockIdx.x * BM; t0 < N; t0 += gridDim.x * BM) {
        __syncthreads();  // protect As from previous tile's readers
        // Stage A tile: pure uint4 copies from pre-split planes (no cvt).
        for (int i = tid; i < BM * CHUNK; i += 256) {
            int r = i / CHUNK, c8 = (i % CHUNK) * 8;
            size_t gg = (size_t)(t0 + r) * KP + c8;   // rows < NPAD always
            *(uint4*)&As_hi[r * SAh + c8] = *(const uint4*)&g_ahi[gg];
            *(uint4*)&As_lo[r * SAh + c8] = *(const uint4*)&g_alo[gg];
        }
        __syncthreads();

        float acc[MT][NT][4];
#pragma unroll
        for (int mt = 0; mt < MT; mt++)
#pragma unroll
            for (int nt = 0; nt < NT; nt++)
#pragma unroll
                for (int j = 0; j < 4; j++) acc[mt][nt][j] = 0.f;

#pragma unroll 2
        for (int k0 = 0; k0 < KP; k0 += 16) {
            uint32_t kb = k0 * 2;  // byte offset along k
            uint32_t ah[MT][4], al[MT][4];
#pragma unroll
            for (int mt = 0; mt < MT; mt++) {
                ldsm_x4(ah[mt][0], ah[mt][1], ah[mt][2], ah[mt][3], aHi[mt] + kb);
                ldsm_x4(al[mt][0], al[mt][1], al[mt][2], al[mt][3], aLo[mt] + kb);
            }
            uint32_t bh[NT][2], bl[NT][2];
#pragma unroll
            for (int p = 0; p < NP; p++) {
                ldsm_x4(bh[2 * p][0], bh[2 * p][1], bh[2 * p + 1][0], bh[2 * p + 1][1],
                        bHi[p] + kb);
                ldsm_x4(bl[2 * p][0], bl[2 * p][1], bl[2 * p + 1][0], bl[2 * p + 1][1],
                        bLo[p] + kb);
            }
#pragma unroll
            for (int nt = 0; nt < NT; nt++) {
#pragma unroll
                for (int mt = 0; mt < MT; mt++) {
                    // corrections first, main term last
                    mma_f16(acc[mt][nt], al[mt][0], al[mt][1], al[mt][2], al[mt][3],
                            bh[nt][0], bh[nt][1]);
                    mma_f16(acc[mt][nt], ah[mt][0], ah[mt][1], ah[mt][2], ah[mt][3],
                            bl[nt][0], bl[nt][1]);
                    mma_f16(acc[mt][nt], ah[mt][0], ah[mt][1], ah[mt][2], ah[mt][3],
                            bh[nt][0], bh[nt][1]);
                }
            }
        }

        // Epilogue
#pragma unroll
        for (int mt = 0; mt < MT; mt++) {
            int r0 = t0 + wr * 32 + mt * 16 + gid;  // c0/c1 row
            int r1 = r0 + 8;                        // c2/c3 row
#pragma unroll
            for (int nt = 0; nt < NT; nt++) {
                int col = wc * WCOLS + nt * 8 + 2 * tig;
                float o0 = acc[mt][nt][0] + bs0[nt];
                float o1 = acc[mt][nt][1] + bs1[nt];
                float o2 = acc[mt][nt][2] + bs0[nt];
                float o3 = acc[mt][nt][3] + bs1[nt];
                if (EPI == 1) {
                    o0 = fmaxf(o0, 0.f); o1 = fmaxf(o1, 0.f);
                    o2 = fmaxf(o2, 0.f); o3 = fmaxf(o3, 0.f);
                }
                if (r0 < N) {
                    if (EPI == 2) {
                        sS[nt * 2]     += o0; sQ[nt * 2]     += o0 * o0;
                        sS[nt * 2 + 1] += o1; sQ[nt * 2 + 1] += o1 * o1;
                    }
                    *(float2*)&outp[(size_t)r0 * COLS + col] = make_float2(o0, o1);
                }
                if (r1 < N) {
                    if (EPI == 2) {
                        sS[nt * 2]     += o2; sQ[nt * 2]     += o2 * o2;
                        sS[nt * 2 + 1] += o3; sQ[nt * 2 + 1] += o3 * o3;
                    }
                    *(float2*)&outp[(size_t)r1 * COLS + col] = make_float2(o2, o3);
                }
            }
        }
    }

    if (EPI == 2) {
        // Lanes sharing a column are {tig, tig+4, ..., tig+28}: xor-reduce 4,8,16
#pragma unroll
        for (int j = 0; j < NT * 2; j++) {
            float s = sS[j], q = sQ[j];
#pragma unroll
            for (int o = 4; o < 32; o <<= 1) {
                s += __shfl_xor_sync(0xffffffffu, s, o);
                q += __shfl_xor_sync(0xffffffffu, q, o);
            }
            if (gid == 0) {
                int col = wc * WCOLS + (j >> 1) * 8 + 2 * tig + (j & 1);
                atomicAdd(&statS[col], s);
                atomicAdd(&statQ[col], q);
            }
        }
    }
}

// ---------------------------------------------------------------------------
// BN finalize: alpha = gamma * rsqrt(var + eps), beta' = beta - mean*alpha
// ---------------------------------------------------------------------------
__global__ void k_bnfin(const float* __restrict__ s, const float* __restrict__ q,
                        const float* __restrict__ gam, const float* __restrict__ bet,
                        float* __restrict__ al, float* __restrict__ bt,
                        int C, float invN) {
    int c = threadIdx.x;
    if (c < C) {
        float m = s[c] * invN;
        float v = q[c] * invN - m * m;
        float a = gam[c] * rsqrtf(v + 1e-5f);
        al[c] = a;
        bt[c] = bet[c] - m * a;
    }
}

// ---------------------------------------------------------------------------
// Final head: out[i] = relu(BN2(t2[i])) . W3 + b3   (warp per node)
// ---------------------------------------------------------------------------
__global__ void k_final(const float* __restrict__ W3, const float* __restrict__ b3,
                        float* __restrict__ out, int N) {
    int g = blockIdx.x * blockDim.x + threadIdx.x;
    int w = g >> 5;
    int lane = g & 31;
    if (w >= N) return;
    float ta = g_t2[(size_t)w * 64 + lane];
    float tb = g_t2[(size_t)w * 64 + 32 + lane];
    float za = fmaxf(ta * g_al2[lane] + g_bt2[lane], 0.f);
    float zb = fmaxf(tb * g_al2[lane + 32] + g_bt2[lane + 32], 0.f);
    float p = za * W3[lane] + zb * W3[lane + 32];
#pragma unroll
    for (int o = 16; o > 0; o >>= 1) p += __shfl_xor_sync(0xffffffffu, p, o);
    if (lane == 0) out[w] = p + b3[0];
}

// ---------------------------------------------------------------------------
// Host launcher
// ---------------------------------------------------------------------------
extern "C" void kernel_launch(void* const* d_in, const int* in_sizes, int n_in,
                              void* d_out, int out_size) {
    const float* x   = (const float*)d_in[0];
    const int*   ei  = (const int*)d_in[1];
    const float* Wl1 = (const float*)d_in[2];
    const float* bl1 = (const float*)d_in[3];
    const float* Wr1 = (const float*)d_in[4];
    const float* Wl2 = (const float*)d_in[5];
    const float* bl2 = (const float*)d_in[6];
    const float* Wr2 = (const float*)d_in[7];
    const float* W1  = (const float*)d_in[8];
    const float* b1  = (const float*)d_in[9];
    const float* g1  = (const float*)d_in[10];
    const float* be1 = (const float*)d_in[11];
    const float* W2  = (const float*)d_in[12];
    const float* b2  = (const float*)d_in[13];
    const float* g2  = (const float*)d_in[14];
    const float* be2 = (const float*)d_in[15];
    const float* W3  = (const float*)d_in[16];
    const float* b3  = (const float*)d_in[17];

    int N = in_sizes[0] / 100;
    int E = in_sizes[1] / 2;
    const int* src = ei;
    const int* dst = ei + E;

    float* out = (float*)d_out;
    float* h1  = out + N;
    float* h2  = h1 + (size_t)N * 128;

    // Scratch symbol addresses
    float *p_t1, *p_t2, *p_s1, *p_q1, *p_s2, *p_q2, *p_al1, *p_bt1, *p_al2, *p_bt2;
    cudaGetSymbolAddress((void**)&p_t1, g_t1);
    cudaGetSymbolAddress((void**)&p_t2, g_t2);
    cudaGetSymbolAddress((void**)&p_s1, g_s1);
    cudaGetSymbolAddress((void**)&p_q1, g_q1);
    cudaGetSymbolAddress((void**)&p_s2, g_s2);
    cudaGetSymbolAddress((void**)&p_q2, g_q2);
    cudaGetSymbolAddress((void**)&p_al1, g_al1);
    cudaGetSymbolAddress((void**)&p_bt1, g_bt1);
    cudaGetSymbolAddress((void**)&p_al2, g_al2);
    cudaGetSymbolAddress((void**)&p_bt2, g_bt2);

    // Dynamic SMEM: (2*COLS + 2*64) * SAh * 2 bytes
    const int SM_SAGE = 384 * 264 * 2;  // KP=208/256 -> SAh=264 : 202752
    const int SM_M1   = 384 * 136 * 2;  // KP=128 -> SAh=136     : 104448
    const int SM_M2   = 256 * 136 * 2;  // COLS=64               :  69632

    cudaFuncSetAttribute(k_gemm<208, 100, 100, 128, 1>,
                         cudaFuncAttributeMaxDynamicSharedMemorySize, SM_SAGE);
    cudaFuncSetAttribute(k_gemm<256, 128, 128, 128, 1>,
                         cudaFuncAttributeMaxDynamicSharedMemorySize, SM_SAGE);
    cudaFuncSetAttribute(k_gemm<128, 128, 0, 128, 2>,
                         cudaFuncAttributeMaxDynamicSharedMemorySize, SM_M1);
    cudaFuncSetAttribute(k_gemm<128, 128, 0, 64, 2>,
                         cudaFuncAttributeMaxDynamicSharedMemorySize, SM_M2);

    // --- CSR build (once; reused by both SAGE layers) ---
    k_zero<<<(N + 255) / 256, 256>>>(N);
    k_hist<<<(E + 255) / 256, 256>>>(dst, E);
    k_scan<<<1, 1024>>>(N);
    k_scatter<<<(E + 255) / 256, 256>>>(src, dst, E);

    // --- SAGE layer 1: h1 = relu([mean | x] @ [Wl1 ; Wr1] + bl1) ---
    k_splitx<<<(N * 54 + 255) / 256, 256>>>(x, N);              // x -> cols 100..207 (stride 208)
    k_aggregate<100, 208><<<(N + 7) / 8, 256>>>(x, N);          // mean -> cols 0..99
    k_gemm<208, 100, 100, 128, 1><<<148, 256, SM_SAGE>>>(
        Wl1, Wr1, bl1, h1, nullptr, nullptr, N);

    // --- SAGE layer 2: h2 = relu([mean(h1) | h1] @ [Wl2 ; Wr2] + bl2) ---
    k_split<128, 128, 256><<<(N * 64 + 255) / 256, 256>>>(h1, N);  // h1 -> cols 128..255
    k_aggregate<128, 256><<<(N + 7) / 8, 256>>>(h1, N);            // mean -> cols 0..127
    k_gemm<256, 128, 128, 128, 1><<<148, 256, SM_SAGE>>>(
        Wl2, Wr2, bl2, h2, nullptr, nullptr, N);

    // --- MLP layer 1 (pre-BN t1 + column stats) ---
    k_split<128, 0, 128><<<(N * 64 + 255) / 256, 256>>>(h2, N);    // h2 -> stride 128
    k_gemm<128, 128, 0, 128, 2><<<296, 256, SM_M1>>>(
        W1, nullptr, b1, p_t1, p_s1, p_q1, N);
    k_bnfin<<<1, 128>>>(p_s1, p_q1, g1, be1, p_al1, p_bt1, 128, 1.f / (float)N);

    // --- MLP layer 2 (BN1+relu applied in split pass; pre-BN t2 + stats) ---
    k_splitbn<<<(N * 64 + 255) / 256, 256>>>(p_t1, p_al1, p_bt1, N);
    k_gemm<128, 128, 0, 64, 2><<<444, 256, SM_M2>>>(
        W2, nullptr, b2, p_t2, p_s2, p_q2, N);
    k_bnfin<<<1, 64>>>(p_s2, p_q2, g2, be2, p_al2, p_bt2, 64, 1.f / (float)N);

    // --- Head: BN2+relu+dot fused ---
    k_final<<<(N + 7) / 8, 256>>>(W3, b3, out, N);
}

// round 14
// speedup vs baseline: 1.8849x; 1.0739x over previous
// rev: R14 — cp.async double-buffered GEMM (BM=32) + epilogue-fused split planes
#include <cuda_runtime.h>
#include <cuda_fp16.h>
#include <cstdint>

#define NMAX 50000
#define EMAX 800000
#define NPAD 50048   // multiple of 32 (and 64)

// ---------------------------------------------------------------------------
// Scratch (static __device__ arrays — no allocation allowed)
// ---------------------------------------------------------------------------
__device__ int    g_count[NMAX];
__device__ int    g_rowptr[NMAX + 1];
__device__ int    g_cursor[NMAX];
__device__ int    g_esrc[EMAX];
// Pre-split fp16 hi/lo A-operand planes, one pair per layout (disjoint buffers
// so epilogue-fused split writes never race with same-buffer reads):
__device__ __half g_a1hi[(size_t)NPAD * 208], g_a1lo[(size_t)NPAD * 208]; // sage1 in
__device__ __half g_a2hi[(size_t)NPAD * 256], g_a2lo[(size_t)NPAD * 256]; // sage2 in
__device__ __half g_a3hi[(size_t)NPAD * 128], g_a3lo[(size_t)NPAD * 128]; // mlp in
__device__ float  g_t1[(size_t)NMAX * 128];   // pre-BN MLP1 activations
__device__ float  g_t2[(size_t)NMAX * 64];    // pre-BN MLP2 activations
__device__ float  g_s1[128], g_q1[128], g_s2[64], g_q2[64];     // BN sums / sumsq
__device__ float  g_al1[128], g_bt1[128], g_al2[64], g_bt2[64]; // BN affine

// ---------------------------------------------------------------------------
// fp16 split helpers (Markidis split: v = hi + lo)
// ---------------------------------------------------------------------------
__device__ __forceinline__ void split2(float v0, float v1, uint32_t& hi, uint32_t& lo) {
    __half2 h = __floats2half2_rn(v0, v1);
    float2 hf = __half22float2(h);
    __half2 l = __floats2half2_rn(v0 - hf.x, v1 - hf.y);
    hi = *(uint32_t*)&h;
    lo = *(uint32_t*)&l;
}
__device__ __forceinline__ void split_store(__half* hi_p, __half* lo_p,
                                            float v0, float v1) {
    uint32_t hi, lo;
    split2(v0, v1, hi, lo);
    *(uint32_t*)hi_p = hi;
    *(uint32_t*)lo_p = lo;
}
__device__ __forceinline__ uint32_t sm_u32(const void* p) {
    return (uint32_t)__cvta_generic_to_shared(p);
}
__device__ __forceinline__ void ldsm_x4(uint32_t& r0, uint32_t& r1,
                                        uint32_t& r2, uint32_t& r3, uint32_t addr) {
    asm volatile("ldmatrix.sync.aligned.m8n8.x4.shared.b16 {%0,%1,%2,%3}, [%4];"
                 : "=r"(r0), "=r"(r1), "=r"(r2), "=r"(r3) : "r"(addr));
}
__device__ __forceinline__ void mma_f16(float* c,
                                        uint32_t a0, uint32_t a1, uint32_t a2, uint32_t a3,
                                        uint32_t b0, uint32_t b1) {
    asm volatile(
        "mma.sync.aligned.m16n8k16.row.col.f32.f16.f16.f32 "
        "{%0,%1,%2,%3}, {%4,%5,%6,%7}, {%8,%9}, {%0,%1,%2,%3};"
        : "+f"(c[0]), "+f"(c[1]), "+f"(c[2]), "+f"(c[3])
        : "r"(a0), "r"(a1), "r"(a2), "r"(a3), "r"(b0), "r"(b1));
}
__device__ __forceinline__ void cp16(uint32_t smem, const void* g) {
    asm volatile("cp.async.cg.shared.global [%0], [%1], 16;" :: "r"(smem), "l"(g) : "memory");
}
__device__ __forceinline__ void cpcommit() {
    asm volatile("cp.async.commit_group;" ::: "memory");
}
template <int NW>
__device__ __forceinline__ void cpwait() {
    asm volatile("cp.async.wait_group %0;" :: "n"(NW) : "memory");
}

// ---------------------------------------------------------------------------
// CSR build: zero -> histogram -> scan -> scatter
// ---------------------------------------------------------------------------
__global__ void k_zero(int n) {
    int i = blockIdx.x * blockDim.x + threadIdx.x;
    if (i < n) g_count[i] = 0;
    if (i < 128) { g_s1[i] = 0.f; g_q1[i] = 0.f; }
    if (i < 64)  { g_s2[i] = 0.f; g_q2[i] = 0.f; }
}

__global__ void k_hist(const int* __restrict__ dst, int E) {
    int i = blockIdx.x * blockDim.x + threadIdx.x;
    if (i < E) atomicAdd(&g_count[dst[i]], 1);
}

__global__ void k_scan(int N) {
    __shared__ int sums[1024];
    int t = threadIdx.x;
    int chunk = (N + 1023) >> 10;
    int b = t * chunk;
    int e = b + chunk; if (e > N) e = N;
    int s = 0;
    for (int i = b; i < e; i++) s += g_count[i];
    sums[t] = s;
    __syncthreads();
    int own = s;
    for (int off = 1; off < 1024; off <<= 1) {
        int v = (t >= off) ? sums[t - off] : 0;
        __syncthreads();
        sums[t] += v;
        __syncthreads();
    }
    int pre = sums[t] - own;  // exclusive prefix
    for (int i = b; i < e; i++) {
        g_rowptr[i] = pre;
        g_cursor[i] = pre;
        pre += g_count[i];
    }
    if (t == 1023) g_rowptr[N] = sums[1023];
}

__global__ void k_scatter(const int* __restrict__ src, const int* __restrict__ dst, int E) {
    int i = blockIdx.x * blockDim.x + threadIdx.x;
    if (i < E) {
        int d = dst[i];
        int p = atomicAdd(&g_cursor[d], 1);
        g_esrc[p] = src[i];
    }
}

// ---------------------------------------------------------------------------
// Split passes (memory-bound; conversions hidden under load/store latency)
// ---------------------------------------------------------------------------
// x: F=100 -> bufA cols [100,208) stride 208 (cols 200..207 zero-padded)
__global__ void k_splitx(const float* __restrict__ x,
                         __half* __restrict__ hi, __half* __restrict__ lo, int N) {
    int i = blockIdx.x * blockDim.x + threadIdx.x;
    int r = i / 54, k2 = i % 54;
    if (r >= N) return;
    float v0 = 0.f, v1 = 0.f;
    if (k2 < 50) {
        float2 v = *(const float2*)&x[(size_t)r * 100 + 2 * k2];
        v0 = v.x; v1 = v.y;
    }
    size_t off = (size_t)r * 208 + 100 + 2 * k2;
    split_store(&hi[off], &lo[off], v0, v1);
}

// bn-relu(t1) -> bufC (stride 128)
__global__ void k_splitbn(const float* __restrict__ src,
                          const float* __restrict__ alpha, const float* __restrict__ beta,
                          __half* __restrict__ hi, __half* __restrict__ lo, int N) {
    int i = blockIdx.x * blockDim.x + threadIdx.x;
    int r = i / 64, k2 = i % 64;
    if (r >= N) return;
    int k = 2 * k2;
    float2 v = *(const float2*)&src[(size_t)r * 128 + k];
    float v0 = fmaxf(fmaf(v.x, alpha[k], beta[k]), 0.f);
    float v1 = fmaxf(fmaf(v.y, alpha[k + 1], beta[k + 1]), 0.f);
    size_t off = (size_t)r * 128 + k;
    split_store(&hi[off], &lo[off], v0, v1);
}

// ---------------------------------------------------------------------------
// Mean aggregation: warp per node, CSR gather, x4 unroll; epilogue writes the
// mean directly as split hi/lo planes at cols [0,F) of the stride-KP buffer.
// ---------------------------------------------------------------------------
template <int F, int KP>
__global__ void k_aggregate(const float* __restrict__ feat,
                            __half* __restrict__ mhi, __half* __restrict__ mlo, int N) {
    int g = blockIdx.x * blockDim.x + threadIdx.x;
    int w = g >> 5;
    int lane = g & 31;
    if (w >= N) return;
    int s = g_rowptr[w], e = g_rowptr[w + 1];
    constexpr int Q = F / 4;
    bool act = (lane < Q);
    int col = lane * 4;
    float ax = 0.f, ay = 0.f, az = 0.f, aw = 0.f;
    int i = s;
    for (; i + 3 < e; i += 4) {
        int s0 = g_esrc[i], s1 = g_esrc[i + 1], s2 = g_esrc[i + 2], s3 = g_esrc[i + 3];
        if (act) {
            float4 v0 = *(const float4*)&feat[(size_t)s0 * F + col];
            float4 v1 = *(const float4*)&feat[(size_t)s1 * F + col];
            float4 v2 = *(const float4*)&feat[(size_t)s2 * F + col];
            float4 v3 = *(const float4*)&feat[(size_t)s3 * F + col];
            ax += v0.x + v1.x + v2.x + v3.x;
            ay += v0.y + v1.y + v2.y + v3.y;
            az += v0.z + v1.z + v2.z + v3.z;
            aw += v0.w + v1.w + v2.w + v3.w;
        }
    }
    for (; i < e; i++) {
        int s0 = g_esrc[i];
        if (act) {
            float4 v = *(const float4*)&feat[(size_t)s0 * F + col];
            ax += v.x; ay += v.y; az += v.z; aw += v.w;
        }
    }
    if (act) {
        float inv = (e > s) ? 1.f / (float)(e - s) : 0.f;  // deg=0 -> mean=0
        uint32_t h0, l0, h1, l1;
        split2(ax * inv, ay * inv, h0, l0);
        split2(az * inv, aw * inv, h1, l1);
        size_t off = (size_t)w * KP + col;   // 8B aligned
        *(uint2*)&mhi[off] = make_uint2(h0, h1);
        *(uint2*)&mlo[off] = make_uint2(l0, l1);
    }
}

// ---------------------------------------------------------------------------
// Fused tensor-core GEMM, split-FP16, pre-split A, cp.async double-buffered:
//   out[N, COLS] = epi( A @ [Wa ; Wb] + bias )
//   EPI 1 (RELU):  relu store; optionally writes split hi/lo planes (Shi/Slo)
//   EPI 2 (STATS): raw store + per-column sum/sumsq accumulation
// Block tile 32 x COLS (BM=32), 2-stage A pipeline overlaps LDGSTS with MMA.
// COLS=128: 8 col-groups x 1 row-group (MT=2); COLS=64: 4x2 (MT=1).
// SAh % 64 == 8 -> ldmatrix conflict-free. 3 MMAs per k16-step.
// ---------------------------------------------------------------------------
template <int KP, int KWA, int KWB, int COLS, int EPI>
__global__ void __launch_bounds__(256)
k_gemm(const __half* __restrict__ Ahi, const __half* __restrict__ Alo,
       const float* __restrict__ Wa, const float* __restrict__ Wb,
       const float* __restrict__ bias,
       float* __restrict__ outp,
       float* __restrict__ statS, float* __restrict__ statQ,
       __half* __restrict__ Shi, __half* __restrict__ Slo, int SKP, int SOFF,
       int N) {
    constexpr int K    = KWA + KWB;
    constexpr int KP2  = KP / 2;
    constexpr int SAh  = ((KP - 8 + 63) / 64) * 64 + 8; // %64 == 8
    constexpr int BM   = 32;
    constexpr int CHUNK = KP / 8;                        // uint4 per A row
    constexpr int CG   = (COLS == 128) ? 8 : 4;          // col-groups
    constexpr int RG   = 8 / CG;                         // row-groups
    constexpr int MT   = 2 / RG;                         // m16 tiles per warp
    constexpr int WCOLS = COLS / CG;                     // 16
    constexpr int NT   = WCOLS / 8;                      // 2
    constexpr int KSTEPS = KP / 16;

    extern __shared__ __half sm_h[];
    __half* Wt_hi = sm_h;                    // [COLS][SAh]
    __half* Wt_lo = Wt_hi + COLS * SAh;
    __half* As    = Wt_lo + COLS * SAh;      // [2 stages][2 planes][BM][SAh]
    constexpr int STAGE = 2 * BM * SAh;      // halves per stage

    int tid = threadIdx.x;
    int lane = tid & 31, wid = tid >> 5;
    int wc, wr;
    if (RG == 1) { wc = wid; wr = 0; }
    else         { wc = wid >> 1; wr = wid & 1; }
    int rowbase = wr * 16 * MT;
    int gid = lane >> 2, tig = lane & 3;

    // Stage W once (transposed [col][k], hi/lo split). Coalesced over columns.
    for (int i = tid; i < COLS * KP2; i += 256) {
        int k2 = i / COLS, c = i % COLS;
        int k = k2 * 2;
        float v0 = 0.f, v1 = 0.f;
        if (k < KWA) {
            v0 = Wa[k * COLS + c];
            v1 = Wa[(k + 1) * COLS + c];
        } else if (KWB > 0 && k < K) {
            v0 = Wb[(k - KWA) * COLS + c];
            v1 = Wb[(k - KWA + 1) * COLS + c];
        }
        split_store(Wt_hi + c * SAh + k, Wt_lo + c * SAh + k, v0, v1);
    }

    // ldmatrix base addresses (k0/stage-independent parts)
    uint32_t aOff[MT];
#pragma unroll
    for (int mt = 0; mt < MT; mt++) {
        int row = rowbase + mt * 16 + (lane & 15);
        aOff[mt] = sm_u32(As + row * SAh + (lane >> 4) * 8);
    }
    uint32_t bHi, bLo;
    {
        int col = wc * WCOLS + ((lane >> 4) & 1) * 8 + (lane & 7);
        int off = col * SAh + ((lane >> 3) & 1) * 8;
        bHi = sm_u32(Wt_hi + off);
        bLo = sm_u32(Wt_lo + off);
    }

    // Bias cache
    float bs0[NT], bs1[NT];
#pragma unroll
    for (int nt = 0; nt < NT; nt++) {
        int c = wc * WCOLS + nt * 8 + 2 * tig;
        bs0[nt] = bias[c];
        bs1[nt] = bias[c + 1];
    }

    float sS[NT * 2], sQ[NT * 2];
#pragma unroll
    for (int j = 0; j < NT * 2; j++) { sS[j] = 0.f; sQ[j] = 0.f; }

    int ntiles = (N + BM - 1) / BM;
    int nloc = ((int)blockIdx.x < ntiles)
                   ? (ntiles - (int)blockIdx.x + (int)gridDim.x - 1) / (int)gridDim.x : 0;

    auto prefetch = [&](int li, int stage) {
        int t0 = ((int)blockIdx.x + li * (int)gridDim.x) * BM;
        __half* dst = As + stage * STAGE;
        for (int j = tid; j < 2 * BM * CHUNK; j += 256) {
            int plane = (j >= BM * CHUNK) ? 1 : 0;
            int rem = j - plane * BM * CHUNK;
            int r = rem / CHUNK, c8 = (rem % CHUNK) * 8;
            const __half* g = (plane ? Alo : Ahi) + (size_t)(t0 + r) * KP + c8;
            cp16(sm_u32(dst + plane * BM * SAh + r * SAh + c8), g);
        }
    };

    if (nloc > 0) { prefetch(0, 0); }
    cpcommit();

    for (int li = 0; li < nloc; li++) {
        int t0 = ((int)blockIdx.x + li * (int)gridDim.x) * BM;
        bool more = (li + 1 < nloc);
        if (more) { prefetch(li + 1, (li + 1) & 1); cpcommit(); }
        if (more) cpwait<1>(); else cpwait<0>();
        __syncthreads();   // A stage ready for all warps (also orders W on li==0)

        uint32_t stageB = (uint32_t)((li & 1) * STAGE * 2);  // byte offset

        float acc[MT][NT][4];
#pragma unroll
        for (int mt = 0; mt < MT; mt++)
#pragma unroll
            for (int nt = 0; nt < NT; nt++)
#pragma unroll
                for (int j = 0; j < 4; j++) acc[mt][nt][j] = 0.f;

#pragma unroll 2
        for (int k0 = 0; k0 < KSTEPS * 16; k0 += 16) {
            uint32_t kb = k0 * 2;
            uint32_t ah[MT][4], al[MT][4];
#pragma unroll
            for (int mt = 0; mt < MT; mt++) {
                ldsm_x4(ah[mt][0], ah[mt][1], ah[mt][2], ah[mt][3],
                        aOff[mt] + stageB + kb);
                ldsm_x4(al[mt][0], al[mt][1], al[mt][2], al[mt][3],
                        aOff[mt] + stageB + (uint32_t)(BM * SAh * 2) + kb);
            }
            uint32_t bh[NT][2], bl[NT][2];
            ldsm_x4(bh[0][0], bh[0][1], bh[1][0], bh[1][1], bHi + kb);
            ldsm_x4(bl[0][0], bl[0][1], bl[1][0], bl[1][1], bLo + kb);
#pragma unroll
            for (int nt = 0; nt < NT; nt++) {
#pragma unroll
                for (int mt = 0; mt < MT; mt++) {
                    mma_f16(acc[mt][nt], al[mt][0], al[mt][1], al[mt][2], al[mt][3],
                            bh[nt][0], bh[nt][1]);
                    mma_f16(acc[mt][nt], ah[mt][0], ah[mt][1], ah[mt][2], ah[mt][3],
                            bl[nt][0], bl[nt][1]);
                    mma_f16(acc[mt][nt], ah[mt][0], ah[mt][1], ah[mt][2], ah[mt][3],
                            bh[nt][0], bh[nt][1]);
                }
            }
        }

        // Epilogue
#pragma unroll
        for (int mt = 0; mt < MT; mt++) {
            int r0 = t0 + rowbase + mt * 16 + gid;
            int r1 = r0 + 8;
#pragma unroll
            for (int nt = 0; nt < NT; nt++) {
                int col = wc * WCOLS + nt * 8 + 2 * tig;
                float o0 = acc[mt][nt][0] + bs0[nt];
                float o1 = acc[mt][nt][1] + bs1[nt];
                float o2 = acc[mt][nt][2] + bs0[nt];
                float o3 = acc[mt][nt][3] + bs1[nt];
                if (EPI == 1) {
                    o0 = fmaxf(o0, 0.f); o1 = fmaxf(o1, 0.f);
                    o2 = fmaxf(o2, 0.f); o3 = fmaxf(o3, 0.f);
                }
                if (r0 < N) {
                    if (EPI == 2) {
                        sS[nt * 2]     += o0; sQ[nt * 2]     += o0 * o0;
                        sS[nt * 2 + 1] += o1; sQ[nt * 2 + 1] += o1 * o1;
                    }
                    *(float2*)&outp[(size_t)r0 * COLS + col] = make_float2(o0, o1);
                    if (EPI == 1 && SKP) {
                        size_t so = (size_t)r0 * SKP + SOFF + col;
                        uint32_t h, l;
                        split2(o0, o1, h, l);
                        *(uint32_t*)&Shi[so] = h;
                        *(uint32_t*)&Slo[so] = l;
                    }
                }
                if (r1 < N) {
                    if (EPI == 2) {
                        sS[nt * 2]     += o2; sQ[nt * 2]     += o2 * o2;
                        sS[nt * 2 + 1] += o3; sQ[nt * 2 + 1] += o3 * o3;
                    }
                    *(float2*)&outp[(size_t)r1 * COLS + col] = make_float2(o2, o3);
                    if (EPI == 1 && SKP) {
                        size_t so = (size_t)r1 * SKP + SOFF + col;
                        uint32_t h, l;
                        split2(o2, o3, h, l);
                        *(uint32_t*)&Shi[so] = h;
                        *(uint32_t*)&Slo[so] = l;
                    }
                }
            }
        }
        __syncthreads();   // all reads of this stage done before it is reused
    }

    if (EPI == 2) {
#pragma unroll
        for (int j = 0; j < NT * 2; j++) {
            float s = sS[j], q = sQ[j];
#pragma unroll
            for (int o = 4; o < 32; o <<= 1) {
                s += __shfl_xor_sync(0xffffffffu, s, o);
                q += __shfl_xor_sync(0xffffffffu, q, o);
            }
            if (gid == 0) {
                int col = wc * WCOLS + (j >> 1) * 8 + 2 * tig + (j & 1);
                atomicAdd(&statS[col], s);
                atomicAdd(&statQ[col], q);
            }
        }
    }
}

// ---------------------------------------------------------------------------
// BN finalize: alpha = gamma * rsqrt(var + eps), beta' = beta - mean*alpha
// ---------------------------------------------------------------------------
__global__ void k_bnfin(const float* __restrict__ s, const float* __restrict__ q,
                        const float* __restrict__ gam, const float* __restrict__ bet,
                        float* __restrict__ al, float* __restrict__ bt,
                        int C, float invN) {
    int c = threadIdx.x;
    if (c < C) {
        float m = s[c] * invN;
        float v = q[c] * invN - m * m;
        float a = gam[c] * rsqrtf(v + 1e-5f);
        al[c] = a;
        bt[c] = bet[c] - m * a;
    }
}

// ---------------------------------------------------------------------------
// Final head: out[i] = relu(BN2(t2[i])) . W3 + b3   (warp per node)
// ---------------------------------------------------------------------------
__global__ void k_final(const float* __restrict__ W3, const float* __restrict__ b3,
                        float* __restrict__ out, int N) {
    int g = blockIdx.x * blockDim.x + threadIdx.x;
    int w = g >> 5;
    int lane = g & 31;
    if (w >= N) return;
    float ta = g_t2[(size_t)w * 64 + lane];
    float tb = g_t2[(size_t)w * 64 + 32 + lane];
    float za = fmaxf(ta * g_al2[lane] + g_bt2[lane], 0.f);
    float zb = fmaxf(tb * g_al2[lane + 32] + g_bt2[lane + 32], 0.f);
    float p = za * W3[lane] + zb * W3[lane + 32];
#pragma unroll
    for (int o = 16; o > 0; o >>= 1) p += __shfl_xor_sync(0xffffffffu, p, o);
    if (lane == 0) out[w] = p + b3[0];
}

// ---------------------------------------------------------------------------
// Host launcher
// ---------------------------------------------------------------------------
extern "C" void kernel_launch(void* const* d_in, const int* in_sizes, int n_in,
                              void* d_out, int out_size) {
    const float* x   = (const float*)d_in[0];
    const int*   ei  = (const int*)d_in[1];
    const float* Wl1 = (const float*)d_in[2];
    const float* bl1 = (const float*)d_in[3];
    const float* Wr1 = (const float*)d_in[4];
    const float* Wl2 = (const float*)d_in[5];
    const float* bl2 = (const float*)d_in[6];
    const float* Wr2 = (const float*)d_in[7];
    const float* W1  = (const float*)d_in[8];
    const float* b1  = (const float*)d_in[9];
    const float* g1  = (const float*)d_in[10];
    const float* be1 = (const float*)d_in[11];
    const float* W2  = (const float*)d_in[12];
    const float* b2  = (const float*)d_in[13];
    const float* g2  = (const float*)d_in[14];
    const float* be2 = (const float*)d_in[15];
    const float* W3  = (const float*)d_in[16];
    const float* b3  = (const float*)d_in[17];

    int N = in_sizes[0] / 100;
    int E = in_sizes[1] / 2;
    const int* src = ei;
    const int* dst = ei + E;

    float* out = (float*)d_out;
    float* h1  = out + N;
    float* h2  = h1 + (size_t)N * 128;

    // Scratch symbol addresses
    __half *a1h, *a1l, *a2h, *a2l, *a3h, *a3l;
    float *p_t1, *p_t2, *p_s1, *p_q1, *p_s2, *p_q2, *p_al1, *p_bt1, *p_al2, *p_bt2;
    cudaGetSymbolAddress((void**)&a1h, g_a1hi);
    cudaGetSymbolAddress((void**)&a1l, g_a1lo);
    cudaGetSymbolAddress((void**)&a2h, g_a2hi);
    cudaGetSymbolAddress((void**)&a2l, g_a2lo);
    cudaGetSymbolAddress((void**)&a3h, g_a3hi);
    cudaGetSymbolAddress((void**)&a3l, g_a3lo);
    cudaGetSymbolAddress((void**)&p_t1, g_t1);
    cudaGetSymbolAddress((void**)&p_t2, g_t2);
    cudaGetSymbolAddress((void**)&p_s1, g_s1);
    cudaGetSymbolAddress((void**)&p_q1, g_q1);
    cudaGetSymbolAddress((void**)&p_s2, g_s2);
    cudaGetSymbolAddress((void**)&p_q2, g_q2);
    cudaGetSymbolAddress((void**)&p_al1, g_al1);
    cudaGetSymbolAddress((void**)&p_bt1, g_bt1);
    cudaGetSymbolAddress((void**)&p_al2, g_al2);
    cudaGetSymbolAddress((void**)&p_bt2, g_bt2);

    // Dynamic SMEM: (2*COLS*SAh + 2 stages * 2 planes * 32 * SAh) * 2 bytes
    const int SM_SAGE = (2 * 128 * 264 + 4 * 32 * 264) * 2;  // 202752
    const int SM_M1   = (2 * 128 * 136 + 4 * 32 * 136) * 2;  // 104448
    const int SM_M2   = (2 * 64 * 136 + 4 * 32 * 136) * 2;   //  69632

    cudaFuncSetAttribute(k_gemm<208, 100, 100, 128, 1>,
                         cudaFuncAttributeMaxDynamicSharedMemorySize, SM_SAGE);
    cudaFuncSetAttribute(k_gemm<256, 128, 128, 128, 1>,
                         cudaFuncAttributeMaxDynamicSharedMemorySize, SM_SAGE);
    cudaFuncSetAttribute(k_gemm<128, 128, 0, 128, 2>,
                         cudaFuncAttributeMaxDynamicSharedMemorySize, SM_M1);
    cudaFuncSetAttribute(k_gemm<128, 128, 0, 64, 2>,
                         cudaFuncAttributeMaxDynamicSharedMemorySize, SM_M2);

    // --- CSR build (once; reused by both SAGE layers) ---
    k_zero<<<(N + 255) / 256, 256>>>(N);
    k_hist<<<(E + 255) / 256, 256>>>(dst, E);
    k_scan<<<1, 1024>>>(N);
    k_scatter<<<(E + 255) / 256, 256>>>(src, dst, E);

    // --- SAGE layer 1: h1 = relu([mean | x] @ [Wl1 ; Wr1] + bl1) ---
    k_splitx<<<(N * 54 + 255) / 256, 256>>>(x, a1h, a1l, N);   // bufA cols 100..207
    k_aggregate<100, 208><<<(N + 7) / 8, 256>>>(x, a1h, a1l, N);
    k_gemm<208, 100, 100, 128, 1><<<148, 256, SM_SAGE>>>(
        a1h, a1l, Wl1, Wr1, bl1, h1, nullptr, nullptr,
        a2h, a2l, 256, 128, N);                                 // fused h1->bufB[128..255]

    // --- SAGE layer 2: h2 = relu([mean(h1) | h1] @ [Wl2 ; Wr2] + bl2) ---
    k_aggregate<128, 256><<<(N + 7) / 8, 256>>>(h1, a2h, a2l, N);
    k_gemm<256, 128, 128, 128, 1><<<148, 256, SM_SAGE>>>(
        a2h, a2l, Wl2, Wr2, bl2, h2, nullptr, nullptr,
        a3h, a3l, 128, 0, N);                                   // fused h2->bufC

    // --- MLP layer 1 (pre-BN t1 + column stats) ---
    k_gemm<128, 128, 0, 128, 2><<<296, 256, SM_M1>>>(
        a3h, a3l, W1, nullptr, b1, p_t1, p_s1, p_q1,
        nullptr, nullptr, 0, 0, N);
    k_bnfin<<<1, 128>>>(p_s1, p_q1, g1, be1, p_al1, p_bt1, 128, 1.f / (float)N);

    // --- MLP layer 2 (BN1+relu applied in split pass; pre-BN t2 + stats) ---
    k_splitbn<<<(N * 64 + 255) / 256, 256>>>(p_t1, p_al1, p_bt1, a3h, a3l, N);
    k_gemm<128, 128, 0, 64, 2><<<444, 256, SM_M2>>>(
        a3h, a3l, W2, nullptr, b2, p_t2, p_s2, p_q2,
        nullptr, nullptr, 0, 0, N);
    k_bnfin<<<1, 64>>>(p_s2, p_q2, g2, be2, p_al2, p_bt2, 64, 1.f / (float)N);

    // --- Head: BN2+relu+dot fused ---
    k_final<<<(N + 7) / 8, 256>>>(W3, b3, out, N);
}